// round 1
// baseline (speedup 1.0000x reference)
#include <cuda_runtime.h>
#include <cstdint>

// ---------------------------------------------------------------------------
// Shapes (fixed by the problem)
// ---------------------------------------------------------------------------
#define TOK    65536     // B*N = total tokens
#define CDIM   256
#define HID    1024

// ---------------------------------------------------------------------------
// Scratch (device globals; allocation inside kernel_launch is forbidden)
// ---------------------------------------------------------------------------
__device__ float g_xqk [TOK*CDIM];
__device__ float g_xv  [TOK*CDIM];
__device__ float g_q   [TOK*CDIM];
__device__ float g_k   [TOK*CDIM];
__device__ float g_v   [TOK*CDIM];
__device__ float g_attn[TOK*CDIM];
__device__ float g_mo  [TOK*CDIM];
__device__ float g_x   [TOK*CDIM];
__device__ float g_ff  [TOK*CDIM];
__device__ float g_y   [TOK*CDIM];
__device__ float g_h   [TOK*HID];

// ---------------------------------------------------------------------------
// GEMM:  C[M,N] = A[M,K] @ B[N,K]^T + bias[N]   (optionally ReLU)
// Tiles: 128(M) x 64(N) x 16(K), 256 threads, 8x4 micro-tile per thread.
// ---------------------------------------------------------------------------
template<int RELU>
__global__ void __launch_bounds__(256)
gemm_nt(const float* __restrict__ A, const float* __restrict__ B,
        const float* __restrict__ bias, float* __restrict__ Cm,
        int M, int N, int K)
{
    __shared__ float As[16][132];   // row stride 132 floats = 528B (16B aligned)
    __shared__ float Bs[16][68];    // row stride 68 floats  = 272B (16B aligned)

    const int bm  = blockIdx.x * 128;
    const int bn  = blockIdx.y * 64;
    const int tid = threadIdx.x;
    const int tx  = tid & 15;    // N direction (16 * 4 = 64)
    const int ty  = tid >> 4;    // M direction (16 * 8 = 128)

    const int arow = tid >> 1;          // 0..127
    const int acol = (tid & 1) * 8;     // 0 or 8
    const int brow = tid >> 2;          // 0..63
    const int bcol = (tid & 3) * 4;     // 0,4,8,12

    float acc[8][4];
    #pragma unroll
    for (int i = 0; i < 8; i++)
        #pragma unroll
        for (int j = 0; j < 4; j++) acc[i][j] = 0.f;

    const float* Aptr = A + (size_t)(bm + arow) * K + acol;
    const float* Bptr = B + (size_t)(bn + brow) * K + bcol;

    for (int k0 = 0; k0 < K; k0 += 16) {
        float4 a0 = *(const float4*)(Aptr + k0);
        float4 a1 = *(const float4*)(Aptr + k0 + 4);
        float4 b0 = *(const float4*)(Bptr + k0);
        As[acol+0][arow] = a0.x; As[acol+1][arow] = a0.y;
        As[acol+2][arow] = a0.z; As[acol+3][arow] = a0.w;
        As[acol+4][arow] = a1.x; As[acol+5][arow] = a1.y;
        As[acol+6][arow] = a1.z; As[acol+7][arow] = a1.w;
        Bs[bcol+0][brow] = b0.x; Bs[bcol+1][brow] = b0.y;
        Bs[bcol+2][brow] = b0.z; Bs[bcol+3][brow] = b0.w;
        __syncthreads();

        #pragma unroll
        for (int k = 0; k < 16; k++) {
            float4 ar0 = *(const float4*)&As[k][ty*8];
            float4 ar1 = *(const float4*)&As[k][ty*8 + 4];
            float4 br  = *(const float4*)&Bs[k][tx*4];
            float am[8] = {ar0.x, ar0.y, ar0.z, ar0.w, ar1.x, ar1.y, ar1.z, ar1.w};
            float bv[4] = {br.x, br.y, br.z, br.w};
            #pragma unroll
            for (int i = 0; i < 8; i++)
                #pragma unroll
                for (int j = 0; j < 4; j++)
                    acc[i][j] += am[i] * bv[j];
        }
        __syncthreads();
    }

    float bb[4];
    #pragma unroll
    for (int j = 0; j < 4; j++) bb[j] = bias[bn + tx*4 + j];

    #pragma unroll
    for (int i = 0; i < 8; i++) {
        int row = bm + ty*8 + i;
        float4 o;
        o.x = acc[i][0] + bb[0];
        o.y = acc[i][1] + bb[1];
        o.z = acc[i][2] + bb[2];
        o.w = acc[i][3] + bb[3];
        if (RELU) {
            o.x = fmaxf(o.x, 0.f); o.y = fmaxf(o.y, 0.f);
            o.z = fmaxf(o.z, 0.f); o.w = fmaxf(o.w, 0.f);
        }
        *(float4*)&Cm[(size_t)row * N + bn + tx*4] = o;
    }
}

// ---------------------------------------------------------------------------
// Attention: one CTA per (batch, head). L in {64, 128}, Dh = 32.
// Q/K/V laid out as [L, BtC, 256] (token-major), head slice h*32..h*32+31.
// ---------------------------------------------------------------------------
template<int L>
__global__ void __launch_bounds__(256)
attn_kernel(const float* __restrict__ Q, const float* __restrict__ K,
            const float* __restrict__ V, float* __restrict__ O, int BtC)
{
    extern __shared__ float sm[];
    float* sq  = sm;                 // [L][36]
    float* skT = sq + L*36;          // [32][L]  (K transposed)
    float* sv  = skT + 32*L;         // [L][36]
    float* ss  = sv + L*36;          // [L][L+1]

    const int bt  = blockIdx.x % BtC;
    const int h   = blockIdx.x / BtC;
    const int tid = threadIdx.x;
    const float scale = 0.17677669529663687f;   // 1/sqrt(32)

    // ---- load Q,K,V tiles ----
    for (int idx = tid; idx < L*8; idx += 256) {
        int l  = idx >> 3;
        int c4 = (idx & 7) * 4;
        size_t g = ((size_t)l * BtC + bt) * 256 + h*32 + c4;
        float4 q4 = *(const float4*)(Q + g);
        float4 k4 = *(const float4*)(K + g);
        float4 v4 = *(const float4*)(V + g);
        sq[l*36 + c4+0] = q4.x; sq[l*36 + c4+1] = q4.y;
        sq[l*36 + c4+2] = q4.z; sq[l*36 + c4+3] = q4.w;
        sv[l*36 + c4+0] = v4.x; sv[l*36 + c4+1] = v4.y;
        sv[l*36 + c4+2] = v4.z; sv[l*36 + c4+3] = v4.w;
        skT[(c4+0)*L + l] = k4.x; skT[(c4+1)*L + l] = k4.y;
        skT[(c4+2)*L + l] = k4.z; skT[(c4+3)*L + l] = k4.w;
    }
    __syncthreads();

    // ---- scores = scale * Q K^T ----
    {
        const int i  = tid % L;
        const int jg = tid / L;
        constexpr int JPT = (L*L)/256;
        float qr[32];
        #pragma unroll
        for (int d = 0; d < 32; d++) qr[d] = sq[i*36 + d];
        #pragma unroll 4
        for (int jj = 0; jj < JPT; jj++) {
            int j = jg*JPT + jj;
            float acc = 0.f;
            #pragma unroll
            for (int d = 0; d < 32; d++) acc += qr[d] * skT[d*L + j];
            ss[i*(L+1) + j] = acc * scale;
        }
    }
    __syncthreads();

    // ---- softmax over rows ----
    {
        const int warp = tid >> 5, lane = tid & 31;
        for (int i = warp; i < L; i += 8) {
            float m = -1e30f;
            #pragma unroll
            for (int j = lane; j < L; j += 32) m = fmaxf(m, ss[i*(L+1)+j]);
            #pragma unroll
            for (int o = 16; o; o >>= 1) m = fmaxf(m, __shfl_xor_sync(~0u, m, o));
            float s = 0.f;
            #pragma unroll
            for (int j = lane; j < L; j += 32) {
                float e = __expf(ss[i*(L+1)+j] - m);
                ss[i*(L+1)+j] = e;
                s += e;
            }
            #pragma unroll
            for (int o = 16; o; o >>= 1) s += __shfl_xor_sync(~0u, s, o);
            float inv = 1.f / s;
            #pragma unroll
            for (int j = lane; j < L; j += 32) ss[i*(L+1)+j] *= inv;
        }
    }
    __syncthreads();

    // ---- O = P V ----
    {
        const int i  = tid % L;
        const int dg = tid / L;
        constexpr int DPT = (32*L)/256;   // 16 for L=128, 8 for L=64
        float acc[DPT];
        #pragma unroll
        for (int d = 0; d < DPT; d++) acc[d] = 0.f;
        for (int j = 0; j < L; j++) {
            float p = ss[i*(L+1) + j];
            #pragma unroll
            for (int d = 0; d < DPT; d++) acc[d] += p * sv[j*36 + dg*DPT + d];
        }
        size_t g = ((size_t)i * BtC + bt) * 256 + h*32 + dg*DPT;
        #pragma unroll
        for (int d = 0; d < DPT; d += 4)
            *(float4*)(O + g + d) = make_float4(acc[d], acc[d+1], acc[d+2], acc[d+3]);
    }
}

// ---------------------------------------------------------------------------
// Gathers (layout permutations fused with +pos)
// ---------------------------------------------------------------------------
// long token t = L*1024 + Bt,  L=(bh,w), Bt=(b,h,ww);  n = bh*1024+h*64+w*8+ww
__global__ void __launch_bounds__(256)
gather_long(const float* __restrict__ src, const float* __restrict__ pos,
            float* __restrict__ xqk, float* __restrict__ xv)
{
    int t  = blockIdx.x * 4 + (threadIdx.x >> 6);
    int c4 = (threadIdx.x & 63) * 4;
    int Lc = t >> 10, Bt = t & 1023;
    int bh = Lc >> 3, w = Lc & 7;
    int b  = Bt >> 7, hh = (Bt >> 3) & 15, ww = Bt & 7;
    int n  = bh*1024 + hh*64 + w*8 + ww;
    float4 s4 = *(const float4*)(src + ((size_t)b*8192 + n)*256 + c4);
    float4 p4 = *(const float4*)(pos + (size_t)n*256 + c4);
    *(float4*)(xv + (size_t)t*256 + c4) = s4;
    float4 o = make_float4(s4.x+p4.x, s4.y+p4.y, s4.z+p4.z, s4.w+p4.w);
    *(float4*)(xqk + (size_t)t*256 + c4) = o;
}

// short token ts = Ls*512 + Bts, Ls=(h2,ww2), Bts=(b2,bh2,w2);
// reads flat long index f = b2*8192 + bh2*1024 + h2*64 + w2*8 + ww2
__global__ void __launch_bounds__(256)
gather_short(const float* __restrict__ mo, const float* __restrict__ pos,
             float* __restrict__ xqk, float* __restrict__ xv)
{
    int ts = blockIdx.x * 4 + (threadIdx.x >> 6);
    int c4 = (threadIdx.x & 63) * 4;
    int Ls = ts >> 9, Bts = ts & 511;
    int h2 = Ls >> 3, ww2 = Ls & 7;
    int b2 = Bts >> 6, bh2 = (Bts >> 3) & 7, w2 = Bts & 7;
    int f  = b2*8192 + bh2*1024 + h2*64 + w2*8 + ww2;
    // pos value at long-flat index f:
    int Lf = f >> 10, r = f & 1023;
    int bh = Lf >> 3, w = Lf & 7, hh = (r >> 3) & 15, ww = r & 7;
    int n  = bh*1024 + hh*64 + w*8 + ww;
    float4 m4 = *(const float4*)(mo  + (size_t)f*256 + c4);
    float4 p4 = *(const float4*)(pos + (size_t)n*256 + c4);
    *(float4*)(xv + (size_t)ts*256 + c4) = m4;
    float4 o = make_float4(m4.x+p4.x, m4.y+p4.y, m4.z+p4.z, m4.w+p4.w);
    *(float4*)(xqk + (size_t)ts*256 + c4) = o;
}

// ---------------------------------------------------------------------------
// Residual + scatter (short layout -> [B,N,C]) + LayerNorm1.   Warp per token.
// ---------------------------------------------------------------------------
__global__ void __launch_bounds__(256)
resid_ln1(const float* __restrict__ src, const float* __restrict__ mo,
          const float* __restrict__ g, const float* __restrict__ be,
          float* __restrict__ out)
{
    int tok  = blockIdx.x * 8 + (threadIdx.x >> 5);
    int lane = threadIdx.x & 31;
    int b = tok >> 13, n = tok & 8191;
    int h2 = n >> 9, bh2 = (n >> 6) & 7, ww2 = (n >> 3) & 7, w2 = n & 7;
    int ts = (h2*8 + ww2)*512 + b*64 + bh2*8 + w2;
    const float* xs = src + (size_t)tok*256;
    const float* ms = mo  + (size_t)ts *256;
    float v[8], sum = 0.f, sq = 0.f;
    #pragma unroll
    for (int i = 0; i < 8; i++) {
        float x = xs[lane + 32*i] + ms[lane + 32*i];
        v[i] = x; sum += x; sq += x*x;
    }
    #pragma unroll
    for (int o = 16; o; o >>= 1) {
        sum += __shfl_xor_sync(~0u, sum, o);
        sq  += __shfl_xor_sync(~0u, sq , o);
    }
    float mu  = sum * (1.f/256.f);
    float var = sq * (1.f/256.f) - mu*mu;
    float inv = rsqrtf(var + 1e-5f);
    #pragma unroll
    for (int i = 0; i < 8; i++) {
        int c = lane + 32*i;
        out[(size_t)tok*256 + c] = (v[i] - mu) * inv * g[c] + be[c];
    }
}

// Residual + LayerNorm2 (both operands in the same [tok,C] layout)
__global__ void __launch_bounds__(256)
add_ln(const float* __restrict__ a, const float* __restrict__ bsrc,
       const float* __restrict__ g, const float* __restrict__ be,
       float* __restrict__ out)
{
    int tok  = blockIdx.x * 8 + (threadIdx.x >> 5);
    int lane = threadIdx.x & 31;
    const float* xa = a    + (size_t)tok*256;
    const float* xb = bsrc + (size_t)tok*256;
    float v[8], sum = 0.f, sq = 0.f;
    #pragma unroll
    for (int i = 0; i < 8; i++) {
        float x = xa[lane + 32*i] + xb[lane + 32*i];
        v[i] = x; sum += x; sq += x*x;
    }
    #pragma unroll
    for (int o = 16; o; o >>= 1) {
        sum += __shfl_xor_sync(~0u, sum, o);
        sq  += __shfl_xor_sync(~0u, sq , o);
    }
    float mu  = sum * (1.f/256.f);
    float var = sq * (1.f/256.f) - mu*mu;
    float inv = rsqrtf(var + 1e-5f);
    #pragma unroll
    for (int i = 0; i < 8; i++) {
        int c = lane + 32*i;
        out[(size_t)tok*256 + c] = (v[i] - mu) * inv * g[c] + be[c];
    }
}

// ---------------------------------------------------------------------------
// Final layout trick: out[b] = x[b]^T viewed as [N,C]  => write [B,C,N]
// ---------------------------------------------------------------------------
__global__ void __launch_bounds__(256)
transpose_out(const float* __restrict__ y, float* __restrict__ out)
{
    __shared__ float tile[32][33];
    int b  = blockIdx.z;
    int n0 = blockIdx.x * 32, c0 = blockIdx.y * 32;
    int tx = threadIdx.x, ty = threadIdx.y;   // 32 x 8
    #pragma unroll
    for (int i = 0; i < 4; i++)
        tile[ty + i*8][tx] = y[((size_t)b*8192 + n0 + ty + i*8)*256 + c0 + tx];
    __syncthreads();
    #pragma unroll
    for (int i = 0; i < 4; i++)
        out[(size_t)b*2097152 + (size_t)(c0 + ty + i*8)*8192 + n0 + tx]
            = tile[tx][ty + i*8];
}

// ---------------------------------------------------------------------------
// Launch
// ---------------------------------------------------------------------------
static inline int attn_smem(int L) { return (L*36*2 + 32*L + L*(L+1)) * 4; }

extern "C" void kernel_launch(void* const* d_in, const int* in_sizes, int n_in,
                              void* d_out, int out_size)
{
    const float* src        = (const float*)d_in[0];
    const float* pos        = (const float*)d_in[1];
    const float* w_in_long  = (const float*)d_in[2];
    const float* b_in_long  = (const float*)d_in[3];
    const float* w_out_long = (const float*)d_in[4];
    const float* b_out_long = (const float*)d_in[5];
    const float* w_in_short = (const float*)d_in[6];
    const float* b_in_short = (const float*)d_in[7];
    const float* w_out_short= (const float*)d_in[8];
    const float* b_out_short= (const float*)d_in[9];
    const float* w1         = (const float*)d_in[10];
    const float* b1         = (const float*)d_in[11];
    const float* w2         = (const float*)d_in[12];
    const float* b2         = (const float*)d_in[13];
    const float* g1         = (const float*)d_in[14];
    const float* beta1      = (const float*)d_in[15];
    const float* g2         = (const float*)d_in[16];
    const float* beta2      = (const float*)d_in[17];
    float* out = (float*)d_out;

    static float *p_xqk=nullptr,*p_xv,*p_q,*p_k,*p_v,*p_attn,*p_mo,*p_x,*p_ff,*p_y,*p_h;
    static bool init_done = false;
    if (!init_done) {
        cudaGetSymbolAddress((void**)&p_xqk , g_xqk );
        cudaGetSymbolAddress((void**)&p_xv  , g_xv  );
        cudaGetSymbolAddress((void**)&p_q   , g_q   );
        cudaGetSymbolAddress((void**)&p_k   , g_k   );
        cudaGetSymbolAddress((void**)&p_v   , g_v   );
        cudaGetSymbolAddress((void**)&p_attn, g_attn);
        cudaGetSymbolAddress((void**)&p_mo  , g_mo  );
        cudaGetSymbolAddress((void**)&p_x   , g_x   );
        cudaGetSymbolAddress((void**)&p_ff  , g_ff  );
        cudaGetSymbolAddress((void**)&p_y   , g_y   );
        cudaGetSymbolAddress((void**)&p_h   , g_h   );
        cudaFuncSetAttribute(attn_kernel<64>,
            cudaFuncAttributeMaxDynamicSharedMemorySize, attn_smem(64));
        cudaFuncSetAttribute(attn_kernel<128>,
            cudaFuncAttributeMaxDynamicSharedMemorySize, attn_smem(128));
        init_done = true;
    }

    const dim3 gemmGrid256(TOK/128, CDIM/64);   // (512, 4)
    const dim3 gemmGridHid(TOK/128, HID /64);   // (512, 16)

    // ---- long-range MHA ----
    gather_long<<<TOK/4, 256>>>(src, pos, p_xqk, p_xv);
    gemm_nt<0><<<gemmGrid256, 256>>>(p_xqk, w_in_long,             b_in_long,       p_q, TOK, CDIM, CDIM);
    gemm_nt<0><<<gemmGrid256, 256>>>(p_xqk, w_in_long + 256*256,   b_in_long + 256, p_k, TOK, CDIM, CDIM);
    gemm_nt<0><<<gemmGrid256, 256>>>(p_xv , w_in_long + 512*256,   b_in_long + 512, p_v, TOK, CDIM, CDIM);
    attn_kernel<64><<<1024*8, 256, attn_smem(64)>>>(p_q, p_k, p_v, p_attn, 1024);
    gemm_nt<0><<<gemmGrid256, 256>>>(p_attn, w_out_long, b_out_long, p_mo, TOK, CDIM, CDIM);

    // ---- short-range MHA ----
    gather_short<<<TOK/4, 256>>>(p_mo, pos, p_xqk, p_xv);
    gemm_nt<0><<<gemmGrid256, 256>>>(p_xqk, w_in_short,            b_in_short,       p_q, TOK, CDIM, CDIM);
    gemm_nt<0><<<gemmGrid256, 256>>>(p_xqk, w_in_short + 256*256,  b_in_short + 256, p_k, TOK, CDIM, CDIM);
    gemm_nt<0><<<gemmGrid256, 256>>>(p_xv , w_in_short + 512*256,  b_in_short + 512, p_v, TOK, CDIM, CDIM);
    attn_kernel<128><<<512*8, 256, attn_smem(128)>>>(p_q, p_k, p_v, p_attn, 512);
    gemm_nt<0><<<gemmGrid256, 256>>>(p_attn, w_out_short, b_out_short, p_mo, TOK, CDIM, CDIM);

    // ---- residual + LN1 ----
    resid_ln1<<<TOK/8, 256>>>(src, p_mo, g1, beta1, p_x);

    // ---- FFN ----
    gemm_nt<1><<<gemmGridHid, 256>>>(p_x, w1, b1, p_h, TOK, HID, CDIM);
    gemm_nt<0><<<gemmGrid256, 256>>>(p_h, w2, b2, p_ff, TOK, CDIM, HID);

    // ---- residual + LN2 ----
    add_ln<<<TOK/8, 256>>>(p_x, p_ff, g2, beta2, p_y);

    // ---- final layout reinterpretation ([B,N,C] -> [B,C,N] flat) ----
    transpose_out<<<dim3(8192/32, 256/32, 8), dim3(32, 8)>>>(p_y, out);
}

// round 2
// speedup vs baseline: 1.2940x; 1.2940x over previous
#include <cuda_runtime.h>
#include <cstdint>

#define TOK    65536
#define CDIM   256
#define HID    1024

// ---------------------------------------------------------------------------
// Scratch
// ---------------------------------------------------------------------------
__device__ float g_xqk [TOK*CDIM];
__device__ float g_xv  [TOK*CDIM];
__device__ float g_q   [TOK*CDIM];
__device__ float g_k   [TOK*CDIM];
__device__ float g_v   [TOK*CDIM];
__device__ float g_attn[TOK*CDIM];
__device__ float g_mo  [TOK*CDIM];
__device__ float g_x   [TOK*CDIM];
__device__ float g_ff  [TOK*CDIM];
__device__ float g_y   [TOK*CDIM];
__device__ float g_h   [TOK*HID];

// ---------------------------------------------------------------------------
// TF32 tensor-core GEMM: C[M,N] = A[M,K] @ B[N,K]^T + bias
// Block tile 128x128x32, 8 warps (2Mx4N), warp tile 64x32 (m16n8k8 frags).
// K-major smem (stride 136 floats -> conflict-free fragment loads).
// EPI: 0 = plain, 1 = ReLU, 2 = fused-QKV split (N=768, three 256-col dsts)
// ---------------------------------------------------------------------------
#define SAS 136                 // smem row stride (floats)
#define TILE_F (32*SAS)         // floats per tile buffer = 4352

__device__ __forceinline__ uint32_t f2tf(float f) {
    uint32_t u;
    asm("cvt.rna.tf32.f32 %0, %1;" : "=r"(u) : "f"(f));
    return u;
}

__device__ __forceinline__ void mma_tf32(float c[4],
    uint32_t a0, uint32_t a1, uint32_t a2, uint32_t a3,
    uint32_t b0, uint32_t b1)
{
    asm volatile(
        "mma.sync.aligned.m16n8k8.row.col.f32.tf32.tf32.f32 "
        "{%0,%1,%2,%3}, {%4,%5,%6,%7}, {%8,%9}, {%0,%1,%2,%3};"
        : "+f"(c[0]), "+f"(c[1]), "+f"(c[2]), "+f"(c[3])
        : "r"(a0), "r"(a1), "r"(a2), "r"(a3), "r"(b0), "r"(b1));
}

template<int EPI>
__global__ void __launch_bounds__(256)
gemm_tc(const float* __restrict__ A0, const float* __restrict__ A1,
        const float* __restrict__ B,  const float* __restrict__ bias,
        float* __restrict__ C0, float* __restrict__ C1, float* __restrict__ C2,
        int M, int N, int K)
{
    extern __shared__ float smem[];
    float* As = smem;               // [2][32][SAS]
    float* Bs = smem + 2*TILE_F;    // [2][32][SAS]

    const int tid = threadIdx.x;
    const int bm  = blockIdx.x * 128;
    const int bnG = blockIdx.y * 128;

    const float* A = A0;
    if (EPI == 2) A = (blockIdx.y < 4) ? A0 : A1;

    // loader mapping: row = tid&127, kc = (tid>>7)*16 (16 consecutive floats)
    const int lr = tid & 127;
    const int kc = (tid >> 7) * 16;
    const float* Ap = A + (size_t)(bm  + lr) * K + kc;
    const float* Bp = B + (size_t)(bnG + lr) * K + kc;

    const int lane = tid & 31, wid = tid >> 5;
    const int g = lane >> 2, t = lane & 3;
    const int wm = (wid >> 2) * 64;   // 0 or 64
    const int wn = (wid & 3) * 32;    // 0,32,64,96

    float acc[4][4][4];
    #pragma unroll
    for (int mi = 0; mi < 4; mi++)
        #pragma unroll
        for (int ni = 0; ni < 4; ni++)
            #pragma unroll
            for (int r = 0; r < 4; r++) acc[mi][ni][r] = 0.f;

    const int KT = K / 32;

    float4 av[4], bv[4];

    // ---- preload tile 0 ----
    #pragma unroll
    for (int j = 0; j < 4; j++) {
        av[j] = *(const float4*)(Ap + j*4);
        bv[j] = *(const float4*)(Bp + j*4);
    }
    #pragma unroll
    for (int j = 0; j < 4; j++) {
        const float* a = &av[j].x;
        const float* b = &bv[j].x;
        #pragma unroll
        for (int e = 0; e < 4; e++) {
            As[(kc + j*4 + e)*SAS + lr] = __uint_as_float(f2tf(a[e]));
            Bs[(kc + j*4 + e)*SAS + lr] = __uint_as_float(f2tf(b[e]));
        }
    }
    __syncthreads();

    for (int kt = 0; kt < KT; kt++) {
        // prefetch next tile into registers
        if (kt + 1 < KT) {
            const float* Apn = Ap + (kt + 1) * 32;
            const float* Bpn = Bp + (kt + 1) * 32;
            #pragma unroll
            for (int j = 0; j < 4; j++) {
                av[j] = *(const float4*)(Apn + j*4);
                bv[j] = *(const float4*)(Bpn + j*4);
            }
        }

        // compute on current buffer
        const float* Ab = As + (kt & 1) * TILE_F;
        const float* Bb = Bs + (kt & 1) * TILE_F;
        #pragma unroll
        for (int ks = 0; ks < 32; ks += 8) {
            uint32_t af[4][4];
            #pragma unroll
            for (int mi = 0; mi < 4; mi++) {
                int mb = wm + mi*16 + g;
                af[mi][0] = __float_as_uint(Ab[(ks + t    )*SAS + mb    ]);
                af[mi][1] = __float_as_uint(Ab[(ks + t    )*SAS + mb + 8]);
                af[mi][2] = __float_as_uint(Ab[(ks + t + 4)*SAS + mb    ]);
                af[mi][3] = __float_as_uint(Ab[(ks + t + 4)*SAS + mb + 8]);
            }
            uint32_t bf[4][2];
            #pragma unroll
            for (int ni = 0; ni < 4; ni++) {
                int nb = wn + ni*8 + g;
                bf[ni][0] = __float_as_uint(Bb[(ks + t    )*SAS + nb]);
                bf[ni][1] = __float_as_uint(Bb[(ks + t + 4)*SAS + nb]);
            }
            #pragma unroll
            for (int mi = 0; mi < 4; mi++)
                #pragma unroll
                for (int ni = 0; ni < 4; ni++)
                    mma_tf32(acc[mi][ni], af[mi][0], af[mi][1], af[mi][2], af[mi][3],
                             bf[ni][0], bf[ni][1]);
        }

        // store next tile into other buffer
        if (kt + 1 < KT) {
            float* Aw = As + ((kt + 1) & 1) * TILE_F;
            float* Bw = Bs + ((kt + 1) & 1) * TILE_F;
            #pragma unroll
            for (int j = 0; j < 4; j++) {
                const float* a = &av[j].x;
                const float* b = &bv[j].x;
                #pragma unroll
                for (int e = 0; e < 4; e++) {
                    Aw[(kc + j*4 + e)*SAS + lr] = __uint_as_float(f2tf(a[e]));
                    Bw[(kc + j*4 + e)*SAS + lr] = __uint_as_float(f2tf(b[e]));
                }
            }
        }
        __syncthreads();
    }

    // ---- epilogue ----
    #pragma unroll
    for (int mi = 0; mi < 4; mi++) {
        #pragma unroll
        for (int ni = 0; ni < 4; ni++) {
            int row0 = bm + wm + mi*16 + g;
            int col  = bnG + wn + ni*8 + t*2;
            float b0 = bias[col], b1 = bias[col + 1];
            float v0 = acc[mi][ni][0] + b0;
            float v1 = acc[mi][ni][1] + b1;
            float v2 = acc[mi][ni][2] + b0;
            float v3 = acc[mi][ni][3] + b1;
            if (EPI == 1) {
                v0 = fmaxf(v0, 0.f); v1 = fmaxf(v1, 0.f);
                v2 = fmaxf(v2, 0.f); v3 = fmaxf(v3, 0.f);
            }
            if (EPI == 2) {
                int region = col >> 8;
                int lc = col & 255;
                float* dst = (region == 0) ? C0 : (region == 1 ? C1 : C2);
                *(float2*)&dst[(size_t)row0      *256 + lc] = make_float2(v0, v1);
                *(float2*)&dst[(size_t)(row0 + 8)*256 + lc] = make_float2(v2, v3);
            } else {
                *(float2*)&C0[(size_t)row0      *N + col] = make_float2(v0, v1);
                *(float2*)&C0[(size_t)(row0 + 8)*N + col] = make_float2(v2, v3);
            }
        }
    }
}

#define GEMM_SMEM (4*TILE_F*4)   // 69632 bytes

// ---------------------------------------------------------------------------
// Attention: one CTA per (batch, head). L in {64, 128}, Dh = 32.
// ---------------------------------------------------------------------------
template<int L>
__global__ void __launch_bounds__(256)
attn_kernel(const float* __restrict__ Q, const float* __restrict__ K,
            const float* __restrict__ V, float* __restrict__ O, int BtC)
{
    extern __shared__ float sm[];
    float* sq  = sm;
    float* skT = sq + L*36;
    float* sv  = skT + 32*L;
    float* ss  = sv + L*36;

    const int bt  = blockIdx.x % BtC;
    const int h   = blockIdx.x / BtC;
    const int tid = threadIdx.x;
    const float scale = 0.17677669529663687f;

    for (int idx = tid; idx < L*8; idx += 256) {
        int l  = idx >> 3;
        int c4 = (idx & 7) * 4;
        size_t gidx = ((size_t)l * BtC + bt) * 256 + h*32 + c4;
        float4 q4 = *(const float4*)(Q + gidx);
        float4 k4 = *(const float4*)(K + gidx);
        float4 v4 = *(const float4*)(V + gidx);
        sq[l*36 + c4+0] = q4.x; sq[l*36 + c4+1] = q4.y;
        sq[l*36 + c4+2] = q4.z; sq[l*36 + c4+3] = q4.w;
        sv[l*36 + c4+0] = v4.x; sv[l*36 + c4+1] = v4.y;
        sv[l*36 + c4+2] = v4.z; sv[l*36 + c4+3] = v4.w;
        skT[(c4+0)*L + l] = k4.x; skT[(c4+1)*L + l] = k4.y;
        skT[(c4+2)*L + l] = k4.z; skT[(c4+3)*L + l] = k4.w;
    }
    __syncthreads();

    {
        const int i  = tid % L;
        const int jg = tid / L;
        constexpr int JPT = (L*L)/256;
        float qr[32];
        #pragma unroll
        for (int d = 0; d < 32; d++) qr[d] = sq[i*36 + d];
        #pragma unroll 4
        for (int jj = 0; jj < JPT; jj++) {
            int j = jg*JPT + jj;
            float acc = 0.f;
            #pragma unroll
            for (int d = 0; d < 32; d++) acc += qr[d] * skT[d*L + j];
            ss[i*(L+1) + j] = acc * scale;
        }
    }
    __syncthreads();

    {
        const int warp = tid >> 5, lane = tid & 31;
        for (int i = warp; i < L; i += 8) {
            float m = -1e30f;
            #pragma unroll
            for (int j = lane; j < L; j += 32) m = fmaxf(m, ss[i*(L+1)+j]);
            #pragma unroll
            for (int o = 16; o; o >>= 1) m = fmaxf(m, __shfl_xor_sync(~0u, m, o));
            float s = 0.f;
            #pragma unroll
            for (int j = lane; j < L; j += 32) {
                float e = __expf(ss[i*(L+1)+j] - m);
                ss[i*(L+1)+j] = e;
                s += e;
            }
            #pragma unroll
            for (int o = 16; o; o >>= 1) s += __shfl_xor_sync(~0u, s, o);
            float inv = 1.f / s;
            #pragma unroll
            for (int j = lane; j < L; j += 32) ss[i*(L+1)+j] *= inv;
        }
    }
    __syncthreads();

    {
        const int i  = tid % L;
        const int dg = tid / L;
        constexpr int DPT = (32*L)/256;
        float acc[DPT];
        #pragma unroll
        for (int d = 0; d < DPT; d++) acc[d] = 0.f;
        for (int j = 0; j < L; j++) {
            float p = ss[i*(L+1) + j];
            #pragma unroll
            for (int d = 0; d < DPT; d++) acc[d] += p * sv[j*36 + dg*DPT + d];
        }
        size_t gidx = ((size_t)i * BtC + bt) * 256 + h*32 + dg*DPT;
        #pragma unroll
        for (int d = 0; d < DPT; d += 4)
            *(float4*)(O + gidx + d) = make_float4(acc[d], acc[d+1], acc[d+2], acc[d+3]);
    }
}

// ---------------------------------------------------------------------------
// Gathers
// ---------------------------------------------------------------------------
__global__ void __launch_bounds__(256)
gather_long(const float* __restrict__ src, const float* __restrict__ pos,
            float* __restrict__ xqk, float* __restrict__ xv)
{
    int t  = blockIdx.x * 4 + (threadIdx.x >> 6);
    int c4 = (threadIdx.x & 63) * 4;
    int Lc = t >> 10, Bt = t & 1023;
    int bh = Lc >> 3, w = Lc & 7;
    int b  = Bt >> 7, hh = (Bt >> 3) & 15, ww = Bt & 7;
    int n  = bh*1024 + hh*64 + w*8 + ww;
    float4 s4 = *(const float4*)(src + ((size_t)b*8192 + n)*256 + c4);
    float4 p4 = *(const float4*)(pos + (size_t)n*256 + c4);
    *(float4*)(xv + (size_t)t*256 + c4) = s4;
    float4 o = make_float4(s4.x+p4.x, s4.y+p4.y, s4.z+p4.z, s4.w+p4.w);
    *(float4*)(xqk + (size_t)t*256 + c4) = o;
}

__global__ void __launch_bounds__(256)
gather_short(const float* __restrict__ mo, const float* __restrict__ pos,
             float* __restrict__ xqk, float* __restrict__ xv)
{
    int ts = blockIdx.x * 4 + (threadIdx.x >> 6);
    int c4 = (threadIdx.x & 63) * 4;
    int Ls = ts >> 9, Bts = ts & 511;
    int h2 = Ls >> 3, ww2 = Ls & 7;
    int b2 = Bts >> 6, bh2 = (Bts >> 3) & 7, w2 = Bts & 7;
    int f  = b2*8192 + bh2*1024 + h2*64 + w2*8 + ww2;
    int Lf = f >> 10, r = f & 1023;
    int bh = Lf >> 3, w = Lf & 7, hh = (r >> 3) & 15, ww = r & 7;
    int n  = bh*1024 + hh*64 + w*8 + ww;
    float4 m4 = *(const float4*)(mo  + (size_t)f*256 + c4);
    float4 p4 = *(const float4*)(pos + (size_t)n*256 + c4);
    *(float4*)(xv + (size_t)ts*256 + c4) = m4;
    float4 o = make_float4(m4.x+p4.x, m4.y+p4.y, m4.z+p4.z, m4.w+p4.w);
    *(float4*)(xqk + (size_t)ts*256 + c4) = o;
}

// ---------------------------------------------------------------------------
// Residual + scatter + LayerNorm
// ---------------------------------------------------------------------------
__global__ void __launch_bounds__(256)
resid_ln1(const float* __restrict__ src, const float* __restrict__ mo,
          const float* __restrict__ g, const float* __restrict__ be,
          float* __restrict__ out)
{
    int tok  = blockIdx.x * 8 + (threadIdx.x >> 5);
    int lane = threadIdx.x & 31;
    int b = tok >> 13, n = tok & 8191;
    int h2 = n >> 9, bh2 = (n >> 6) & 7, ww2 = (n >> 3) & 7, w2 = n & 7;
    int ts = (h2*8 + ww2)*512 + b*64 + bh2*8 + w2;
    const float* xs = src + (size_t)tok*256;
    const float* ms = mo  + (size_t)ts *256;
    float v[8], sum = 0.f, sq = 0.f;
    #pragma unroll
    for (int i = 0; i < 8; i++) {
        float x = xs[lane + 32*i] + ms[lane + 32*i];
        v[i] = x; sum += x; sq += x*x;
    }
    #pragma unroll
    for (int o = 16; o; o >>= 1) {
        sum += __shfl_xor_sync(~0u, sum, o);
        sq  += __shfl_xor_sync(~0u, sq , o);
    }
    float mu  = sum * (1.f/256.f);
    float var = sq * (1.f/256.f) - mu*mu;
    float inv = rsqrtf(var + 1e-5f);
    #pragma unroll
    for (int i = 0; i < 8; i++) {
        int c = lane + 32*i;
        out[(size_t)tok*256 + c] = (v[i] - mu) * inv * g[c] + be[c];
    }
}

__global__ void __launch_bounds__(256)
add_ln(const float* __restrict__ a, const float* __restrict__ bsrc,
       const float* __restrict__ g, const float* __restrict__ be,
       float* __restrict__ out)
{
    int tok  = blockIdx.x * 8 + (threadIdx.x >> 5);
    int lane = threadIdx.x & 31;
    const float* xa = a    + (size_t)tok*256;
    const float* xb = bsrc + (size_t)tok*256;
    float v[8], sum = 0.f, sq = 0.f;
    #pragma unroll
    for (int i = 0; i < 8; i++) {
        float x = xa[lane + 32*i] + xb[lane + 32*i];
        v[i] = x; sum += x; sq += x*x;
    }
    #pragma unroll
    for (int o = 16; o; o >>= 1) {
        sum += __shfl_xor_sync(~0u, sum, o);
        sq  += __shfl_xor_sync(~0u, sq , o);
    }
    float mu  = sum * (1.f/256.f);
    float var = sq * (1.f/256.f) - mu*mu;
    float inv = rsqrtf(var + 1e-5f);
    #pragma unroll
    for (int i = 0; i < 8; i++) {
        int c = lane + 32*i;
        out[(size_t)tok*256 + c] = (v[i] - mu) * inv * g[c] + be[c];
    }
}

__global__ void __launch_bounds__(256)
transpose_out(const float* __restrict__ y, float* __restrict__ out)
{
    __shared__ float tile[32][33];
    int b  = blockIdx.z;
    int n0 = blockIdx.x * 32, c0 = blockIdx.y * 32;
    int tx = threadIdx.x, ty = threadIdx.y;
    #pragma unroll
    for (int i = 0; i < 4; i++)
        tile[ty + i*8][tx] = y[((size_t)b*8192 + n0 + ty + i*8)*256 + c0 + tx];
    __syncthreads();
    #pragma unroll
    for (int i = 0; i < 4; i++)
        out[(size_t)b*2097152 + (size_t)(c0 + ty + i*8)*8192 + n0 + tx]
            = tile[tx][ty + i*8];
}

// ---------------------------------------------------------------------------
// Launch
// ---------------------------------------------------------------------------
static inline int attn_smem(int L) { return (L*36*2 + 32*L + L*(L+1)) * 4; }

extern "C" void kernel_launch(void* const* d_in, const int* in_sizes, int n_in,
                              void* d_out, int out_size)
{
    const float* src        = (const float*)d_in[0];
    const float* pos        = (const float*)d_in[1];
    const float* w_in_long  = (const float*)d_in[2];
    const float* b_in_long  = (const float*)d_in[3];
    const float* w_out_long = (const float*)d_in[4];
    const float* b_out_long = (const float*)d_in[5];
    const float* w_in_short = (const float*)d_in[6];
    const float* b_in_short = (const float*)d_in[7];
    const float* w_out_short= (const float*)d_in[8];
    const float* b_out_short= (const float*)d_in[9];
    const float* w1         = (const float*)d_in[10];
    const float* b1         = (const float*)d_in[11];
    const float* w2         = (const float*)d_in[12];
    const float* b2         = (const float*)d_in[13];
    const float* g1         = (const float*)d_in[14];
    const float* beta1      = (const float*)d_in[15];
    const float* g2         = (const float*)d_in[16];
    const float* beta2      = (const float*)d_in[17];
    float* out = (float*)d_out;

    static float *p_xqk=nullptr,*p_xv,*p_q,*p_k,*p_v,*p_attn,*p_mo,*p_x,*p_ff,*p_y,*p_h;
    static bool init_done = false;
    if (!init_done) {
        cudaGetSymbolAddress((void**)&p_xqk , g_xqk );
        cudaGetSymbolAddress((void**)&p_xv  , g_xv  );
        cudaGetSymbolAddress((void**)&p_q   , g_q   );
        cudaGetSymbolAddress((void**)&p_k   , g_k   );
        cudaGetSymbolAddress((void**)&p_v   , g_v   );
        cudaGetSymbolAddress((void**)&p_attn, g_attn);
        cudaGetSymbolAddress((void**)&p_mo  , g_mo  );
        cudaGetSymbolAddress((void**)&p_x   , g_x   );
        cudaGetSymbolAddress((void**)&p_ff  , g_ff  );
        cudaGetSymbolAddress((void**)&p_y   , g_y   );
        cudaGetSymbolAddress((void**)&p_h   , g_h   );
        cudaFuncSetAttribute(attn_kernel<64>,
            cudaFuncAttributeMaxDynamicSharedMemorySize, attn_smem(64));
        cudaFuncSetAttribute(attn_kernel<128>,
            cudaFuncAttributeMaxDynamicSharedMemorySize, attn_smem(128));
        cudaFuncSetAttribute(gemm_tc<0>,
            cudaFuncAttributeMaxDynamicSharedMemorySize, GEMM_SMEM);
        cudaFuncSetAttribute(gemm_tc<1>,
            cudaFuncAttributeMaxDynamicSharedMemorySize, GEMM_SMEM);
        cudaFuncSetAttribute(gemm_tc<2>,
            cudaFuncAttributeMaxDynamicSharedMemorySize, GEMM_SMEM);
        init_done = true;
    }

    const dim3 gQKV(TOK/128, 6);
    const dim3 g256(TOK/128, 2);
    const dim3 gHID(TOK/128, 8);

    // ---- long-range MHA ----
    gather_long<<<TOK/4, 256>>>(src, pos, p_xqk, p_xv);
    gemm_tc<2><<<gQKV, 256, GEMM_SMEM>>>(p_xqk, p_xv, w_in_long, b_in_long,
                                         p_q, p_k, p_v, TOK, 768, CDIM);
    attn_kernel<64><<<1024*8, 256, attn_smem(64)>>>(p_q, p_k, p_v, p_attn, 1024);
    gemm_tc<0><<<g256, 256, GEMM_SMEM>>>(p_attn, nullptr, w_out_long, b_out_long,
                                         p_mo, nullptr, nullptr, TOK, CDIM, CDIM);

    // ---- short-range MHA ----
    gather_short<<<TOK/4, 256>>>(p_mo, pos, p_xqk, p_xv);
    gemm_tc<2><<<gQKV, 256, GEMM_SMEM>>>(p_xqk, p_xv, w_in_short, b_in_short,
                                         p_q, p_k, p_v, TOK, 768, CDIM);
    attn_kernel<128><<<512*8, 256, attn_smem(128)>>>(p_q, p_k, p_v, p_attn, 512);
    gemm_tc<0><<<g256, 256, GEMM_SMEM>>>(p_attn, nullptr, w_out_short, b_out_short,
                                         p_mo, nullptr, nullptr, TOK, CDIM, CDIM);

    // ---- residual + LN1 ----
    resid_ln1<<<TOK/8, 256>>>(src, p_mo, g1, beta1, p_x);

    // ---- FFN ----
    gemm_tc<1><<<gHID, 256, GEMM_SMEM>>>(p_x, nullptr, w1, b1,
                                         p_h, nullptr, nullptr, TOK, HID, CDIM);
    gemm_tc<0><<<g256, 256, GEMM_SMEM>>>(p_h, nullptr, w2, b2,
                                         p_ff, nullptr, nullptr, TOK, CDIM, HID);

    // ---- residual + LN2 ----
    add_ln<<<TOK/8, 256>>>(p_x, p_ff, g2, beta2, p_y);

    // ---- final layout reinterpretation ----
    transpose_out<<<dim3(8192/32, 256/32, 8), dim3(32, 8)>>>(p_y, out);
}

// round 3
// speedup vs baseline: 1.6649x; 1.2867x over previous
#include <cuda_runtime.h>
#include <cstdint>

#define TOK    65536
#define CDIM   256
#define HID    1024

// ---------------------------------------------------------------------------
// Scratch
// ---------------------------------------------------------------------------
__device__ float g_xqk [TOK*CDIM];
__device__ float g_xv  [TOK*CDIM];
__device__ float g_q   [TOK*CDIM];
__device__ float g_k   [TOK*CDIM];
__device__ float g_v   [TOK*CDIM];
__device__ float g_attn[TOK*CDIM];
__device__ float g_mo  [TOK*CDIM];
__device__ float g_x   [TOK*CDIM];
__device__ float g_ff  [TOK*CDIM];
__device__ float g_y   [TOK*CDIM];
__device__ float g_h   [TOK*HID];

// ---------------------------------------------------------------------------
// TF32 tensor-core GEMM: C[M,N] = A[M,K] @ B[N,K]^T + bias
// Block tile 128x128x32, 8 warps (2Mx4N), warp tile 64x32.
// Row-major smem [row][36] (stride 36 floats -> LDS.128 conflict-free),
// cp.async 2-stage pipeline, k-permuted mma feeding (logical k = 8t+2s+h).
// EPI: 0 = plain, 1 = ReLU, 2 = fused-QKV split (N=768, three 256-col dsts)
// ---------------------------------------------------------------------------
#define ROWF 36                    // floats per smem row
#define STAGE_F (256*ROWF)         // A(128 rows) + B(128 rows) per stage
#define GEMM_SMEM (2*STAGE_F*4)    // 73728 bytes

__device__ __forceinline__ void cpasync16(uint32_t dst, const float* src) {
    asm volatile("cp.async.cg.shared.global [%0], [%1], 16;\n" :: "r"(dst), "l"(src));
}
__device__ __forceinline__ void cp_commit() {
    asm volatile("cp.async.commit_group;\n");
}
template<int N>
__device__ __forceinline__ void cp_wait() {
    asm volatile("cp.async.wait_group %0;\n" :: "n"(N));
}

__device__ __forceinline__ void mma_tf32(float c[4],
    uint32_t a0, uint32_t a1, uint32_t a2, uint32_t a3,
    uint32_t b0, uint32_t b1)
{
    asm volatile(
        "mma.sync.aligned.m16n8k8.row.col.f32.tf32.tf32.f32 "
        "{%0,%1,%2,%3}, {%4,%5,%6,%7}, {%8,%9}, {%0,%1,%2,%3};"
        : "+f"(c[0]), "+f"(c[1]), "+f"(c[2]), "+f"(c[3])
        : "r"(a0), "r"(a1), "r"(a2), "r"(a3), "r"(b0), "r"(b1));
}

template<int EPI>
__global__ void __launch_bounds__(256, 2)
gemm_tc(const float* __restrict__ A0, const float* __restrict__ A1,
        const float* __restrict__ B,  const float* __restrict__ bias,
        float* __restrict__ C0, float* __restrict__ C1, float* __restrict__ C2,
        int M, int N, int K)
{
    extern __shared__ float smem[];

    const int tid = threadIdx.x;
    const int bm  = blockIdx.x * 128;
    const int bnG = blockIdx.y * 128;

    const float* A = A0;
    if (EPI == 2) A = (blockIdx.y < 4) ? A0 : A1;

    // loader: row = tid&127, kc = (tid>>7)*16
    const int lr = tid & 127;
    const int kc = (tid >> 7) * 16;
    const float* Ap = A + (size_t)(bm  + lr) * K + kc;
    const float* Bp = B + (size_t)(bnG + lr) * K + kc;

    uint32_t sb = (uint32_t)__cvta_generic_to_shared(smem);
    const uint32_t dA = sb + (lr*ROWF + kc) * 4;
    const uint32_t dB = sb + ((128 + lr)*ROWF + kc) * 4;

    const int lane = tid & 31, wid = tid >> 5;
    const int g = lane >> 2, t = lane & 3;
    const int wm = (wid >> 2) * 64;   // 0 or 64
    const int wn = (wid & 3) * 32;    // 0,32,64,96

    float acc[4][4][4];
    #pragma unroll
    for (int mi = 0; mi < 4; mi++)
        #pragma unroll
        for (int ni = 0; ni < 4; ni++)
            #pragma unroll
            for (int r = 0; r < 4; r++) acc[mi][ni][r] = 0.f;

    const int KT = K / 32;

    // ---- prologue: stage 0 ----
    #pragma unroll
    for (int j = 0; j < 4; j++) {
        cpasync16(dA + j*16, Ap + j*4);
        cpasync16(dB + j*16, Bp + j*4);
    }
    cp_commit();

    for (int kt = 0; kt < KT; kt++) {
        if (kt + 1 < KT) {
            uint32_t so = (uint32_t)(((kt+1) & 1) * STAGE_F * 4);
            const float* Apn = Ap + (kt+1)*32;
            const float* Bpn = Bp + (kt+1)*32;
            #pragma unroll
            for (int j = 0; j < 4; j++) {
                cpasync16(dA + so + j*16, Apn + j*4);
                cpasync16(dB + so + j*16, Bpn + j*4);
            }
            cp_commit();
            cp_wait<1>();
        } else {
            cp_wait<0>();
        }
        __syncthreads();

        const float* Ab = smem + (kt & 1) * STAGE_F;
        const float* Bb = Ab + 128*ROWF;

        #pragma unroll
        for (int j = 0; j < 2; j++) {          // j = k-half (16 logical k)
            // A fragments: rows wm+mi*16+g (+8), 4 consecutive floats at t*8+j*4
            float4 fa[4][2];
            #pragma unroll
            for (int mi = 0; mi < 4; mi++) {
                int r0 = wm + mi*16 + g;
                fa[mi][0] = *(const float4*)&Ab[r0      *ROWF + t*8 + j*4];
                fa[mi][1] = *(const float4*)&Ab[(r0 + 8)*ROWF + t*8 + j*4];
            }
            float4 fb[4];
            #pragma unroll
            for (int ni = 0; ni < 4; ni++) {
                int nr = wn + ni*8 + g;
                fb[ni] = *(const float4*)&Bb[nr*ROWF + t*8 + j*4];
            }
            #pragma unroll
            for (int s2 = 0; s2 < 2; s2++) {   // s = 2j + s2 ; c = 2*s2
                #pragma unroll
                for (int mi = 0; mi < 4; mi++) {
                    const float* a0p = &fa[mi][0].x;
                    const float* a1p = &fa[mi][1].x;
                    uint32_t a0 = __float_as_uint(a0p[s2*2    ]);
                    uint32_t a2 = __float_as_uint(a0p[s2*2 + 1]);
                    uint32_t a1 = __float_as_uint(a1p[s2*2    ]);
                    uint32_t a3 = __float_as_uint(a1p[s2*2 + 1]);
                    #pragma unroll
                    for (int ni = 0; ni < 4; ni++) {
                        const float* bp = &fb[ni].x;
                        uint32_t b0 = __float_as_uint(bp[s2*2    ]);
                        uint32_t b1 = __float_as_uint(bp[s2*2 + 1]);
                        mma_tf32(acc[mi][ni], a0, a1, a2, a3, b0, b1);
                    }
                }
            }
        }
        __syncthreads();
    }

    // ---- epilogue ----
    #pragma unroll
    for (int mi = 0; mi < 4; mi++) {
        #pragma unroll
        for (int ni = 0; ni < 4; ni++) {
            int row0 = bm + wm + mi*16 + g;
            int col  = bnG + wn + ni*8 + t*2;
            float b0 = bias[col], b1 = bias[col + 1];
            float v0 = acc[mi][ni][0] + b0;
            float v1 = acc[mi][ni][1] + b1;
            float v2 = acc[mi][ni][2] + b0;
            float v3 = acc[mi][ni][3] + b1;
            if (EPI == 1) {
                v0 = fmaxf(v0, 0.f); v1 = fmaxf(v1, 0.f);
                v2 = fmaxf(v2, 0.f); v3 = fmaxf(v3, 0.f);
            }
            if (EPI == 2) {
                int region = col >> 8;
                int lc = col & 255;
                float* dst = (region == 0) ? C0 : (region == 1 ? C1 : C2);
                *(float2*)&dst[(size_t)row0      *256 + lc] = make_float2(v0, v1);
                *(float2*)&dst[(size_t)(row0 + 8)*256 + lc] = make_float2(v2, v3);
            } else {
                *(float2*)&C0[(size_t)row0      *N + col] = make_float2(v0, v1);
                *(float2*)&C0[(size_t)(row0 + 8)*N + col] = make_float2(v2, v3);
            }
        }
    }
}

// ---------------------------------------------------------------------------
// Attention: one CTA per (batch, head). L in {64, 128}, Dh = 32.
// ---------------------------------------------------------------------------
template<int L>
__global__ void __launch_bounds__(256)
attn_kernel(const float* __restrict__ Q, const float* __restrict__ K,
            const float* __restrict__ V, float* __restrict__ O, int BtC)
{
    extern __shared__ float sm[];
    float* sq  = sm;
    float* skT = sq + L*36;
    float* sv  = skT + 32*L;
    float* ss  = sv + L*36;

    const int bt  = blockIdx.x % BtC;
    const int h   = blockIdx.x / BtC;
    const int tid = threadIdx.x;
    const float scale = 0.17677669529663687f;

    for (int idx = tid; idx < L*8; idx += 256) {
        int l  = idx >> 3;
        int c4 = (idx & 7) * 4;
        size_t gidx = ((size_t)l * BtC + bt) * 256 + h*32 + c4;
        float4 q4 = *(const float4*)(Q + gidx);
        float4 k4 = *(const float4*)(K + gidx);
        float4 v4 = *(const float4*)(V + gidx);
        sq[l*36 + c4+0] = q4.x; sq[l*36 + c4+1] = q4.y;
        sq[l*36 + c4+2] = q4.z; sq[l*36 + c4+3] = q4.w;
        sv[l*36 + c4+0] = v4.x; sv[l*36 + c4+1] = v4.y;
        sv[l*36 + c4+2] = v4.z; sv[l*36 + c4+3] = v4.w;
        skT[(c4+0)*L + l] = k4.x; skT[(c4+1)*L + l] = k4.y;
        skT[(c4+2)*L + l] = k4.z; skT[(c4+3)*L + l] = k4.w;
    }
    __syncthreads();

    {
        const int i  = tid % L;
        const int jg = tid / L;
        constexpr int JPT = (L*L)/256;
        float qr[32];
        #pragma unroll
        for (int d = 0; d < 32; d++) qr[d] = sq[i*36 + d];
        #pragma unroll 4
        for (int jj = 0; jj < JPT; jj++) {
            int j = jg*JPT + jj;
            float acc = 0.f;
            #pragma unroll
            for (int d = 0; d < 32; d++) acc += qr[d] * skT[d*L + j];
            ss[i*(L+1) + j] = acc * scale;
        }
    }
    __syncthreads();

    {
        const int warp = tid >> 5, lane = tid & 31;
        for (int i = warp; i < L; i += 8) {
            float m = -1e30f;
            #pragma unroll
            for (int j = lane; j < L; j += 32) m = fmaxf(m, ss[i*(L+1)+j]);
            #pragma unroll
            for (int o = 16; o; o >>= 1) m = fmaxf(m, __shfl_xor_sync(~0u, m, o));
            float s = 0.f;
            #pragma unroll
            for (int j = lane; j < L; j += 32) {
                float e = __expf(ss[i*(L+1)+j] - m);
                ss[i*(L+1)+j] = e;
                s += e;
            }
            #pragma unroll
            for (int o = 16; o; o >>= 1) s += __shfl_xor_sync(~0u, s, o);
            float inv = 1.f / s;
            #pragma unroll
            for (int j = lane; j < L; j += 32) ss[i*(L+1)+j] *= inv;
        }
    }
    __syncthreads();

    {
        const int i  = tid % L;
        const int dg = tid / L;
        constexpr int DPT = (32*L)/256;
        float acc[DPT];
        #pragma unroll
        for (int d = 0; d < DPT; d++) acc[d] = 0.f;
        for (int j = 0; j < L; j++) {
            float p = ss[i*(L+1) + j];
            #pragma unroll
            for (int d = 0; d < DPT; d++) acc[d] += p * sv[j*36 + dg*DPT + d];
        }
        size_t gidx = ((size_t)i * BtC + bt) * 256 + h*32 + dg*DPT;
        #pragma unroll
        for (int d = 0; d < DPT; d += 4)
            *(float4*)(O + gidx + d) = make_float4(acc[d], acc[d+1], acc[d+2], acc[d+3]);
    }
}

// ---------------------------------------------------------------------------
// Gathers
// ---------------------------------------------------------------------------
__global__ void __launch_bounds__(256)
gather_long(const float* __restrict__ src, const float* __restrict__ pos,
            float* __restrict__ xqk, float* __restrict__ xv)
{
    int t  = blockIdx.x * 4 + (threadIdx.x >> 6);
    int c4 = (threadIdx.x & 63) * 4;
    int Lc = t >> 10, Bt = t & 1023;
    int bh = Lc >> 3, w = Lc & 7;
    int b  = Bt >> 7, hh = (Bt >> 3) & 15, ww = Bt & 7;
    int n  = bh*1024 + hh*64 + w*8 + ww;
    float4 s4 = *(const float4*)(src + ((size_t)b*8192 + n)*256 + c4);
    float4 p4 = *(const float4*)(pos + (size_t)n*256 + c4);
    *(float4*)(xv + (size_t)t*256 + c4) = s4;
    float4 o = make_float4(s4.x+p4.x, s4.y+p4.y, s4.z+p4.z, s4.w+p4.w);
    *(float4*)(xqk + (size_t)t*256 + c4) = o;
}

__global__ void __launch_bounds__(256)
gather_short(const float* __restrict__ mo, const float* __restrict__ pos,
             float* __restrict__ xqk, float* __restrict__ xv)
{
    int ts = blockIdx.x * 4 + (threadIdx.x >> 6);
    int c4 = (threadIdx.x & 63) * 4;
    int Ls = ts >> 9, Bts = ts & 511;
    int h2 = Ls >> 3, ww2 = Ls & 7;
    int b2 = Bts >> 6, bh2 = (Bts >> 3) & 7, w2 = Bts & 7;
    int f  = b2*8192 + bh2*1024 + h2*64 + w2*8 + ww2;
    int Lf = f >> 10, r = f & 1023;
    int bh = Lf >> 3, w = Lf & 7, hh = (r >> 3) & 15, ww = r & 7;
    int n  = bh*1024 + hh*64 + w*8 + ww;
    float4 m4 = *(const float4*)(mo  + (size_t)f*256 + c4);
    float4 p4 = *(const float4*)(pos + (size_t)n*256 + c4);
    *(float4*)(xv + (size_t)ts*256 + c4) = m4;
    float4 o = make_float4(m4.x+p4.x, m4.y+p4.y, m4.z+p4.z, m4.w+p4.w);
    *(float4*)(xqk + (size_t)ts*256 + c4) = o;
}

// ---------------------------------------------------------------------------
// Residual + scatter + LayerNorm
// ---------------------------------------------------------------------------
__global__ void __launch_bounds__(256)
resid_ln1(const float* __restrict__ src, const float* __restrict__ mo,
          const float* __restrict__ g, const float* __restrict__ be,
          float* __restrict__ out)
{
    int tok  = blockIdx.x * 8 + (threadIdx.x >> 5);
    int lane = threadIdx.x & 31;
    int b = tok >> 13, n = tok & 8191;
    int h2 = n >> 9, bh2 = (n >> 6) & 7, ww2 = (n >> 3) & 7, w2 = n & 7;
    int ts = (h2*8 + ww2)*512 + b*64 + bh2*8 + w2;
    const float* xs = src + (size_t)tok*256;
    const float* ms = mo  + (size_t)ts *256;
    float v[8], sum = 0.f, sq = 0.f;
    #pragma unroll
    for (int i = 0; i < 8; i++) {
        float x = xs[lane + 32*i] + ms[lane + 32*i];
        v[i] = x; sum += x; sq += x*x;
    }
    #pragma unroll
    for (int o = 16; o; o >>= 1) {
        sum += __shfl_xor_sync(~0u, sum, o);
        sq  += __shfl_xor_sync(~0u, sq , o);
    }
    float mu  = sum * (1.f/256.f);
    float var = sq * (1.f/256.f) - mu*mu;
    float inv = rsqrtf(var + 1e-5f);
    #pragma unroll
    for (int i = 0; i < 8; i++) {
        int c = lane + 32*i;
        out[(size_t)tok*256 + c] = (v[i] - mu) * inv * g[c] + be[c];
    }
}

__global__ void __launch_bounds__(256)
add_ln(const float* __restrict__ a, const float* __restrict__ bsrc,
       const float* __restrict__ g, const float* __restrict__ be,
       float* __restrict__ out)
{
    int tok  = blockIdx.x * 8 + (threadIdx.x >> 5);
    int lane = threadIdx.x & 31;
    const float* xa = a    + (size_t)tok*256;
    const float* xb = bsrc + (size_t)tok*256;
    float v[8], sum = 0.f, sq = 0.f;
    #pragma unroll
    for (int i = 0; i < 8; i++) {
        float x = xa[lane + 32*i] + xb[lane + 32*i];
        v[i] = x; sum += x; sq += x*x;
    }
    #pragma unroll
    for (int o = 16; o; o >>= 1) {
        sum += __shfl_xor_sync(~0u, sum, o);
        sq  += __shfl_xor_sync(~0u, sq , o);
    }
    float mu  = sum * (1.f/256.f);
    float var = sq * (1.f/256.f) - mu*mu;
    float inv = rsqrtf(var + 1e-5f);
    #pragma unroll
    for (int i = 0; i < 8; i++) {
        int c = lane + 32*i;
        out[(size_t)tok*256 + c] = (v[i] - mu) * inv * g[c] + be[c];
    }
}

__global__ void __launch_bounds__(256)
transpose_out(const float* __restrict__ y, float* __restrict__ out)
{
    __shared__ float tile[32][33];
    int b  = blockIdx.z;
    int n0 = blockIdx.x * 32, c0 = blockIdx.y * 32;
    int tx = threadIdx.x, ty = threadIdx.y;
    #pragma unroll
    for (int i = 0; i < 4; i++)
        tile[ty + i*8][tx] = y[((size_t)b*8192 + n0 + ty + i*8)*256 + c0 + tx];
    __syncthreads();
    #pragma unroll
    for (int i = 0; i < 4; i++)
        out[(size_t)b*2097152 + (size_t)(c0 + ty + i*8)*8192 + n0 + tx]
            = tile[tx][ty + i*8];
}

// ---------------------------------------------------------------------------
// Launch
// ---------------------------------------------------------------------------
static inline int attn_smem(int L) { return (L*36*2 + 32*L + L*(L+1)) * 4; }

extern "C" void kernel_launch(void* const* d_in, const int* in_sizes, int n_in,
                              void* d_out, int out_size)
{
    const float* src        = (const float*)d_in[0];
    const float* pos        = (const float*)d_in[1];
    const float* w_in_long  = (const float*)d_in[2];
    const float* b_in_long  = (const float*)d_in[3];
    const float* w_out_long = (const float*)d_in[4];
    const float* b_out_long = (const float*)d_in[5];
    const float* w_in_short = (const float*)d_in[6];
    const float* b_in_short = (const float*)d_in[7];
    const float* w_out_short= (const float*)d_in[8];
    const float* b_out_short= (const float*)d_in[9];
    const float* w1         = (const float*)d_in[10];
    const float* b1         = (const float*)d_in[11];
    const float* w2         = (const float*)d_in[12];
    const float* b2         = (const float*)d_in[13];
    const float* g1         = (const float*)d_in[14];
    const float* beta1      = (const float*)d_in[15];
    const float* g2         = (const float*)d_in[16];
    const float* beta2      = (const float*)d_in[17];
    float* out = (float*)d_out;

    static float *p_xqk=nullptr,*p_xv,*p_q,*p_k,*p_v,*p_attn,*p_mo,*p_x,*p_ff,*p_y,*p_h;
    static bool init_done = false;
    if (!init_done) {
        cudaGetSymbolAddress((void**)&p_xqk , g_xqk );
        cudaGetSymbolAddress((void**)&p_xv  , g_xv  );
        cudaGetSymbolAddress((void**)&p_q   , g_q   );
        cudaGetSymbolAddress((void**)&p_k   , g_k   );
        cudaGetSymbolAddress((void**)&p_v   , g_v   );
        cudaGetSymbolAddress((void**)&p_attn, g_attn);
        cudaGetSymbolAddress((void**)&p_mo  , g_mo  );
        cudaGetSymbolAddress((void**)&p_x   , g_x   );
        cudaGetSymbolAddress((void**)&p_ff  , g_ff  );
        cudaGetSymbolAddress((void**)&p_y   , g_y   );
        cudaGetSymbolAddress((void**)&p_h   , g_h   );
        cudaFuncSetAttribute(attn_kernel<64>,
            cudaFuncAttributeMaxDynamicSharedMemorySize, attn_smem(64));
        cudaFuncSetAttribute(attn_kernel<128>,
            cudaFuncAttributeMaxDynamicSharedMemorySize, attn_smem(128));
        cudaFuncSetAttribute(gemm_tc<0>,
            cudaFuncAttributeMaxDynamicSharedMemorySize, GEMM_SMEM);
        cudaFuncSetAttribute(gemm_tc<1>,
            cudaFuncAttributeMaxDynamicSharedMemorySize, GEMM_SMEM);
        cudaFuncSetAttribute(gemm_tc<2>,
            cudaFuncAttributeMaxDynamicSharedMemorySize, GEMM_SMEM);
        init_done = true;
    }

    const dim3 gQKV(TOK/128, 6);
    const dim3 g256(TOK/128, 2);
    const dim3 gHID(TOK/128, 8);

    // ---- long-range MHA ----
    gather_long<<<TOK/4, 256>>>(src, pos, p_xqk, p_xv);
    gemm_tc<2><<<gQKV, 256, GEMM_SMEM>>>(p_xqk, p_xv, w_in_long, b_in_long,
                                         p_q, p_k, p_v, TOK, 768, CDIM);
    attn_kernel<64><<<1024*8, 256, attn_smem(64)>>>(p_q, p_k, p_v, p_attn, 1024);
    gemm_tc<0><<<g256, 256, GEMM_SMEM>>>(p_attn, nullptr, w_out_long, b_out_long,
                                         p_mo, nullptr, nullptr, TOK, CDIM, CDIM);

    // ---- short-range MHA ----
    gather_short<<<TOK/4, 256>>>(p_mo, pos, p_xqk, p_xv);
    gemm_tc<2><<<gQKV, 256, GEMM_SMEM>>>(p_xqk, p_xv, w_in_short, b_in_short,
                                         p_q, p_k, p_v, TOK, 768, CDIM);
    attn_kernel<128><<<512*8, 256, attn_smem(128)>>>(p_q, p_k, p_v, p_attn, 512);
    gemm_tc<0><<<g256, 256, GEMM_SMEM>>>(p_attn, nullptr, w_out_short, b_out_short,
                                         p_mo, nullptr, nullptr, TOK, CDIM, CDIM);

    // ---- residual + LN1 ----
    resid_ln1<<<TOK/8, 256>>>(src, p_mo, g1, beta1, p_x);

    // ---- FFN ----
    gemm_tc<1><<<gHID, 256, GEMM_SMEM>>>(p_x, nullptr, w1, b1,
                                         p_h, nullptr, nullptr, TOK, HID, CDIM);
    gemm_tc<0><<<g256, 256, GEMM_SMEM>>>(p_h, nullptr, w2, b2,
                                         p_ff, nullptr, nullptr, TOK, CDIM, HID);

    // ---- residual + LN2 ----
    add_ln<<<TOK/8, 256>>>(p_x, p_ff, g2, beta2, p_y);

    // ---- final layout reinterpretation ----
    transpose_out<<<dim3(8192/32, 256/32, 8), dim3(32, 8)>>>(p_y, out);
}

// round 6
// speedup vs baseline: 2.8938x; 1.7381x over previous
#include <cuda_runtime.h>
#include <cuda_fp16.h>
#include <cstdint>

#define TOK    65536
#define CDIM   256
#define HID    1024

// ---------------------------------------------------------------------------
// Scratch (fp16 activations for GEMM operands; fp32 where residual precision
// matters)
// ---------------------------------------------------------------------------
__device__ __half g_xqk [TOK*CDIM];
__device__ __half g_xv  [TOK*CDIM];
__device__ __half g_q   [TOK*CDIM];
__device__ __half g_k   [TOK*CDIM];
__device__ __half g_v   [TOK*CDIM];
__device__ __half g_attn[TOK*CDIM];
__device__ float  g_mo  [TOK*CDIM];
__device__ float  g_x   [TOK*CDIM];
__device__ __half g_x16 [TOK*CDIM];
__device__ __half g_h   [TOK*HID];
__device__ float  g_ff  [TOK*CDIM];
__device__ float  g_y   [TOK*CDIM];
// fp16 weights (converted each launch)
__device__ __half g_wl [768*256];
__device__ __half g_wol[256*256];
__device__ __half g_ws [768*256];
__device__ __half g_wos[256*256];
__device__ __half g_w1h[HID*256];
__device__ __half g_w2h[256*HID];

// ---------------------------------------------------------------------------
// PTX helpers
// ---------------------------------------------------------------------------
__device__ __forceinline__ void cpasync16(uint32_t dst, const void* src) {
    asm volatile("cp.async.cg.shared.global [%0], [%1], 16;\n" :: "r"(dst), "l"(src));
}
__device__ __forceinline__ void cp_commit() {
    asm volatile("cp.async.commit_group;\n");
}
template<int N>
__device__ __forceinline__ void cp_wait() {
    asm volatile("cp.async.wait_group %0;\n" :: "n"(N));
}
__device__ __forceinline__ void ldsm4(uint32_t& r0, uint32_t& r1,
                                      uint32_t& r2, uint32_t& r3, uint32_t addr) {
    asm volatile("ldmatrix.sync.aligned.m8n8.x4.shared.b16 {%0,%1,%2,%3}, [%4];"
                 : "=r"(r0), "=r"(r1), "=r"(r2), "=r"(r3) : "r"(addr));
}
__device__ __forceinline__ void mma16816(float c[4],
    uint32_t a0, uint32_t a1, uint32_t a2, uint32_t a3, uint32_t b0, uint32_t b1)
{
    asm volatile(
        "mma.sync.aligned.m16n8k16.row.col.f32.f16.f16.f32 "
        "{%0,%1,%2,%3}, {%4,%5,%6,%7}, {%8,%9}, {%0,%1,%2,%3};"
        : "+f"(c[0]), "+f"(c[1]), "+f"(c[2]), "+f"(c[3])
        : "r"(a0), "r"(a1), "r"(a2), "r"(a3), "r"(b0), "r"(b1));
}
__device__ __forceinline__ uint32_t pack2(float a, float b) {
    __half2 h = __floats2half2_rn(a, b);
    return *(uint32_t*)&h;
}

// ---------------------------------------------------------------------------
// FP16 tensor-core GEMM: C[M,N] = A[M,K] @ B[N,K]^T + bias
// Block 128x128, K-chunk 64 halves (128B rows, XOR swizzle), 8 warps (2Mx4N),
// 3-stage cp.async pipeline, ONE __syncthreads per chunk, ldmatrix fragments.
// EPI: 0 plain, 1 ReLU, 2 fused-QKV split.  OUTH: 1 -> fp16 C, 0 -> fp32 C.
// ---------------------------------------------------------------------------
#define STAGE_B 32768            // A 16KB + B 16KB
#define GEMMH_SMEM (3*STAGE_B)   // 98304

__device__ __forceinline__ void load_chunk16(const __half* __restrict__ A,
                                             const __half* __restrict__ B,
                                             int bm, int bn, int K, int kt,
                                             uint32_t sbase, int tid)
{
    #pragma unroll
    for (int j = 0; j < 4; j++) {
        int idx = tid*4 + j;
        int row = idx >> 3, c = idx & 7;
        uint32_t off = (uint32_t)(row*128 + ((c ^ (row & 7)) << 4));
        cpasync16(sbase + off, A + (size_t)(bm + row)*K + kt*64 + c*8);
    }
    #pragma unroll
    for (int j = 0; j < 4; j++) {
        int idx = tid*4 + j;
        int row = idx >> 3, c = idx & 7;
        uint32_t off = (uint32_t)(row*128 + ((c ^ (row & 7)) << 4));
        cpasync16(sbase + 16384 + off, B + (size_t)(bn + row)*K + kt*64 + c*8);
    }
    cp_commit();
}

template<int EPI, int OUTH>
__global__ void __launch_bounds__(256, 2)
gemm_h(const __half* __restrict__ A0, const __half* __restrict__ A1,
       const __half* __restrict__ B,  const float* __restrict__ bias,
       void* C0, void* C1, void* C2, int M, int N, int K)
{
    extern __shared__ __align__(128) char dsm[];
    const int tid = threadIdx.x;
    const int bm  = blockIdx.x * 128;
    const int bnG = blockIdx.y * 128;

    const __half* A = A0;
    if (EPI == 2) A = (blockIdx.y < 4) ? A0 : A1;

    uint32_t sb = (uint32_t)__cvta_generic_to_shared(dsm);

    const int lane = tid & 31, wid = tid >> 5;
    const int wm = (wid >> 2) * 64;
    const int wn = (wid & 3) * 32;
    const int lq = lane >> 3;     // quad 0..3
    const int l7 = lane & 7;

    float acc[4][4][4];
    #pragma unroll
    for (int mi = 0; mi < 4; mi++)
        #pragma unroll
        for (int ni = 0; ni < 4; ni++)
            #pragma unroll
            for (int r = 0; r < 4; r++) acc[mi][ni][r] = 0.f;

    const int KT = K / 64;

    load_chunk16(A, B, bm, bnG, K, 0, sb,           tid);
    load_chunk16(A, B, bm, bnG, K, 1, sb + STAGE_B, tid);

    // per-lane ldmatrix row precompute
    int arow[4], brow[2];
    #pragma unroll
    for (int mi = 0; mi < 4; mi++) arow[mi] = wm + mi*16 + (lq & 1)*8 + l7;
    #pragma unroll
    for (int p = 0; p < 2; p++)    brow[p]  = wn + p*16 + (lq >> 1)*8 + l7;
    const int aqh = lq >> 1;       // A k-half select
    const int bqh = lq & 1;        // B k-half select

    for (int kt = 0; kt < KT; kt++) {
        if (kt + 2 < KT) cp_wait<1>(); else cp_wait<0>();
        __syncthreads();
        if (kt + 2 < KT)
            load_chunk16(A, B, bm, bnG, K, kt + 2,
                         sb + (uint32_t)((kt + 2) % 3)*STAGE_B, tid);

        uint32_t Ab = sb + (uint32_t)(kt % 3)*STAGE_B;
        uint32_t Bb = Ab + 16384;

        #pragma unroll
        for (int s = 0; s < 4; s++) {
            uint32_t af[4][4];
            #pragma unroll
            for (int mi = 0; mi < 4; mi++) {
                int row = arow[mi];
                uint32_t addr = Ab + (uint32_t)(row*128 +
                                (((2*s + aqh) ^ (row & 7)) << 4));
                ldsm4(af[mi][0], af[mi][1], af[mi][2], af[mi][3], addr);
            }
            uint32_t bf[4][2];
            #pragma unroll
            for (int p = 0; p < 2; p++) {
                int row = brow[p];
                uint32_t addr = Bb + (uint32_t)(row*128 +
                                (((2*s + bqh) ^ (row & 7)) << 4));
                ldsm4(bf[2*p][0], bf[2*p][1], bf[2*p+1][0], bf[2*p+1][1], addr);
            }
            #pragma unroll
            for (int mi = 0; mi < 4; mi++)
                #pragma unroll
                for (int ni = 0; ni < 4; ni++)
                    mma16816(acc[mi][ni], af[mi][0], af[mi][1], af[mi][2], af[mi][3],
                             bf[ni][0], bf[ni][1]);
        }
    }

    // ---- epilogue ----
    const int g2 = lane >> 2, t2 = lane & 3;
    void* dstp = C0;
    int ldc = N, colbase = bnG;
    if (EPI == 2) {
        int region = blockIdx.y >> 1;
        dstp = (region == 0) ? C0 : (region == 1 ? C1 : C2);
        ldc = 256;
        colbase = (blockIdx.y & 1) * 128;
    }

    #pragma unroll
    for (int mi = 0; mi < 4; mi++) {
        #pragma unroll
        for (int ni = 0; ni < 4; ni++) {
            int row = bm + wm + mi*16 + g2;
            int cg  = bnG + wn + ni*8 + t2*2;       // global col (bias index)
            int cl  = colbase + wn + ni*8 + t2*2;   // dst col
            float b0 = bias[cg], b1 = bias[cg + 1];
            float v0 = acc[mi][ni][0] + b0;
            float v1 = acc[mi][ni][1] + b1;
            float v2 = acc[mi][ni][2] + b0;
            float v3 = acc[mi][ni][3] + b1;
            if (EPI == 1) {
                v0 = fmaxf(v0, 0.f); v1 = fmaxf(v1, 0.f);
                v2 = fmaxf(v2, 0.f); v3 = fmaxf(v3, 0.f);
            }
            if (OUTH) {
                __half* d = (__half*)dstp;
                *(__half2*)&d[(size_t)row      *ldc + cl] = __floats2half2_rn(v0, v1);
                *(__half2*)&d[(size_t)(row + 8)*ldc + cl] = __floats2half2_rn(v2, v3);
            } else {
                float* d = (float*)dstp;
                *(float2*)&d[(size_t)row      *ldc + cl] = make_float2(v0, v1);
                *(float2*)&d[(size_t)(row + 8)*ldc + cl] = make_float2(v2, v3);
            }
        }
    }
}

// ---------------------------------------------------------------------------
// Weight fp32 -> fp16 conversion
// ---------------------------------------------------------------------------
__global__ void __launch_bounds__(256)
f2h(const float* __restrict__ s, __half* __restrict__ d, int n)
{
    int i = (blockIdx.x*256 + threadIdx.x) * 4;
    if (i < n) {
        float4 v = *(const float4*)(s + i);
        uint2 o;
        o.x = pack2(v.x, v.y);
        o.y = pack2(v.z, v.w);
        *(uint2*)(d + i) = o;
    }
}

// ---------------------------------------------------------------------------
// Attention: one CTA per (batch, head). L in {64,128}, Dh=32. fp16 I/O.
// ---------------------------------------------------------------------------
template<int L>
__global__ void __launch_bounds__(256)
attn_kernel(const __half* __restrict__ Q, const __half* __restrict__ K,
            const __half* __restrict__ V, __half* __restrict__ O, int BtC)
{
    extern __shared__ float sm[];
    float* sq  = sm;
    float* skT = sq + L*36;
    float* sv  = skT + 32*L;
    float* ss  = sv + L*36;

    const int bt  = blockIdx.x % BtC;
    const int h   = blockIdx.x / BtC;
    const int tid = threadIdx.x;
    const float scale = 0.17677669529663687f;

    for (int idx = tid; idx < L*4; idx += 256) {
        int l  = idx >> 2;
        int c8 = (idx & 3) * 8;
        size_t g0 = ((size_t)l * BtC + bt) * 256 + h*32 + c8;
        uint4 qv = *(const uint4*)(Q + g0);
        uint4 kv = *(const uint4*)(K + g0);
        uint4 vv = *(const uint4*)(V + g0);
        const __half2* qh = (const __half2*)&qv;
        const __half2* kh = (const __half2*)&kv;
        const __half2* vh = (const __half2*)&vv;
        #pragma unroll
        for (int e = 0; e < 4; e++) {
            float2 fq = __half22float2(qh[e]);
            float2 fk = __half22float2(kh[e]);
            float2 fv = __half22float2(vh[e]);
            sq[l*36 + c8 + 2*e    ] = fq.x;
            sq[l*36 + c8 + 2*e + 1] = fq.y;
            sv[l*36 + c8 + 2*e    ] = fv.x;
            sv[l*36 + c8 + 2*e + 1] = fv.y;
            skT[(c8 + 2*e    )*L + l] = fk.x;
            skT[(c8 + 2*e + 1)*L + l] = fk.y;
        }
    }
    __syncthreads();

    {
        const int i  = tid % L;
        const int jg = tid / L;
        constexpr int JPT = (L*L)/256;
        float qr[32];
        #pragma unroll
        for (int d = 0; d < 32; d++) qr[d] = sq[i*36 + d];
        #pragma unroll 4
        for (int jj = 0; jj < JPT; jj++) {
            int j = jg*JPT + jj;
            float acc = 0.f;
            #pragma unroll
            for (int d = 0; d < 32; d++) acc += qr[d] * skT[d*L + j];
            ss[i*(L+1) + j] = acc * scale;
        }
    }
    __syncthreads();

    {
        const int warp = tid >> 5, lane = tid & 31;
        for (int i = warp; i < L; i += 8) {
            float m = -1e30f;
            #pragma unroll
            for (int j = lane; j < L; j += 32) m = fmaxf(m, ss[i*(L+1)+j]);
            #pragma unroll
            for (int o = 16; o; o >>= 1) m = fmaxf(m, __shfl_xor_sync(~0u, m, o));
            float s = 0.f;
            #pragma unroll
            for (int j = lane; j < L; j += 32) {
                float e = __expf(ss[i*(L+1)+j] - m);
                ss[i*(L+1)+j] = e;
                s += e;
            }
            #pragma unroll
            for (int o = 16; o; o >>= 1) s += __shfl_xor_sync(~0u, s, o);
            float inv = 1.f / s;
            #pragma unroll
            for (int j = lane; j < L; j += 32) ss[i*(L+1)+j] *= inv;
        }
    }
    __syncthreads();

    {
        const int i  = tid % L;
        const int dg = tid / L;
        constexpr int DPT = (32*L)/256;   // 8 (L=64) or 16 (L=128)
        float acc[DPT];
        #pragma unroll
        for (int d = 0; d < DPT; d++) acc[d] = 0.f;
        for (int j = 0; j < L; j++) {
            float p = ss[i*(L+1) + j];
            #pragma unroll
            for (int d = 0; d < DPT; d++) acc[d] += p * sv[j*36 + dg*DPT + d];
        }
        size_t g0 = ((size_t)i * BtC + bt) * 256 + h*32 + dg*DPT;
        #pragma unroll
        for (int d = 0; d < DPT; d += 8) {
            uint4 o;
            o.x = pack2(acc[d+0], acc[d+1]);
            o.y = pack2(acc[d+2], acc[d+3]);
            o.z = pack2(acc[d+4], acc[d+5]);
            o.w = pack2(acc[d+6], acc[d+7]);
            *(uint4*)(O + g0 + d) = o;
        }
    }
}

// ---------------------------------------------------------------------------
// Gathers (fp32 in -> fp16 out, fused +pos)
// ---------------------------------------------------------------------------
__global__ void __launch_bounds__(256)
gather_long(const float* __restrict__ src, const float* __restrict__ pos,
            __half* __restrict__ xqk, __half* __restrict__ xv)
{
    int t  = blockIdx.x * 4 + (threadIdx.x >> 6);
    int c4 = (threadIdx.x & 63) * 4;
    int Lc = t >> 10, Bt = t & 1023;
    int bh = Lc >> 3, w = Lc & 7;
    int b  = Bt >> 7, hh = (Bt >> 3) & 15, ww = Bt & 7;
    int n  = bh*1024 + hh*64 + w*8 + ww;
    float4 s4 = *(const float4*)(src + ((size_t)b*8192 + n)*256 + c4);
    float4 p4 = *(const float4*)(pos + (size_t)n*256 + c4);
    uint2 ov; ov.x = pack2(s4.x, s4.y); ov.y = pack2(s4.z, s4.w);
    *(uint2*)(xv + (size_t)t*256 + c4) = ov;
    uint2 oq; oq.x = pack2(s4.x+p4.x, s4.y+p4.y); oq.y = pack2(s4.z+p4.z, s4.w+p4.w);
    *(uint2*)(xqk + (size_t)t*256 + c4) = oq;
}

__global__ void __launch_bounds__(256)
gather_short(const float* __restrict__ mo, const float* __restrict__ pos,
             __half* __restrict__ xqk, __half* __restrict__ xv)
{
    int ts = blockIdx.x * 4 + (threadIdx.x >> 6);
    int c4 = (threadIdx.x & 63) * 4;
    int Ls = ts >> 9, Bts = ts & 511;
    int h2 = Ls >> 3, ww2 = Ls & 7;
    int b2 = Bts >> 6, bh2 = (Bts >> 3) & 7, w2 = Bts & 7;
    int f  = b2*8192 + bh2*1024 + h2*64 + w2*8 + ww2;
    int Lf = f >> 10, r = f & 1023;
    int bh = Lf >> 3, w = Lf & 7, hh = (r >> 3) & 15, ww = r & 7;
    int n  = bh*1024 + hh*64 + w*8 + ww;
    float4 m4 = *(const float4*)(mo  + (size_t)f*256 + c4);
    float4 p4 = *(const float4*)(pos + (size_t)n*256 + c4);
    uint2 ov; ov.x = pack2(m4.x, m4.y); ov.y = pack2(m4.z, m4.w);
    *(uint2*)(xv + (size_t)ts*256 + c4) = ov;
    uint2 oq; oq.x = pack2(m4.x+p4.x, m4.y+p4.y); oq.y = pack2(m4.z+p4.z, m4.w+p4.w);
    *(uint2*)(xqk + (size_t)ts*256 + c4) = oq;
}

// ---------------------------------------------------------------------------
// Residual + scatter + LayerNorm (LN1 also emits fp16 copy for FFN GEMM)
// ---------------------------------------------------------------------------
__global__ void __launch_bounds__(256)
resid_ln1(const float* __restrict__ src, const float* __restrict__ mo,
          const float* __restrict__ g, const float* __restrict__ be,
          float* __restrict__ out, __half* __restrict__ out16)
{
    int tok  = blockIdx.x * 8 + (threadIdx.x >> 5);
    int lane = threadIdx.x & 31;
    int b = tok >> 13, n = tok & 8191;
    int h2 = n >> 9, bh2 = (n >> 6) & 7, ww2 = (n >> 3) & 7, w2 = n & 7;
    int ts = (h2*8 + ww2)*512 + b*64 + bh2*8 + w2;
    const float* xs = src + (size_t)tok*256;
    const float* ms = mo  + (size_t)ts *256;
    float v[8], sum = 0.f, sq = 0.f;
    #pragma unroll
    for (int i = 0; i < 8; i++) {
        float x = xs[lane + 32*i] + ms[lane + 32*i];
        v[i] = x; sum += x; sq += x*x;
    }
    #pragma unroll
    for (int o = 16; o; o >>= 1) {
        sum += __shfl_xor_sync(~0u, sum, o);
        sq  += __shfl_xor_sync(~0u, sq , o);
    }
    float mu  = sum * (1.f/256.f);
    float var = sq * (1.f/256.f) - mu*mu;
    float inv = rsqrtf(var + 1e-5f);
    #pragma unroll
    for (int i = 0; i < 8; i++) {
        int c = lane + 32*i;
        float r = (v[i] - mu) * inv * g[c] + be[c];
        out  [(size_t)tok*256 + c] = r;
        out16[(size_t)tok*256 + c] = __float2half(r);
    }
}

__global__ void __launch_bounds__(256)
add_ln(const float* __restrict__ a, const float* __restrict__ bsrc,
       const float* __restrict__ g, const float* __restrict__ be,
       float* __restrict__ out)
{
    int tok  = blockIdx.x * 8 + (threadIdx.x >> 5);
    int lane = threadIdx.x & 31;
    const float* xa = a    + (size_t)tok*256;
    const float* xb = bsrc + (size_t)tok*256;
    float v[8], sum = 0.f, sq = 0.f;
    #pragma unroll
    for (int i = 0; i < 8; i++) {
        float x = xa[lane + 32*i] + xb[lane + 32*i];
        v[i] = x; sum += x; sq += x*x;
    }
    #pragma unroll
    for (int o = 16; o; o >>= 1) {
        sum += __shfl_xor_sync(~0u, sum, o);
        sq  += __shfl_xor_sync(~0u, sq , o);
    }
    float mu  = sum * (1.f/256.f);
    float var = sq * (1.f/256.f) - mu*mu;
    float inv = rsqrtf(var + 1e-5f);
    #pragma unroll
    for (int i = 0; i < 8; i++) {
        int c = lane + 32*i;
        out[(size_t)tok*256 + c] = (v[i] - mu) * inv * g[c] + be[c];
    }
}

__global__ void __launch_bounds__(256)
transpose_out(const float* __restrict__ y, float* __restrict__ out)
{
    __shared__ float tile[32][33];
    int b  = blockIdx.z;
    int n0 = blockIdx.x * 32, c0 = blockIdx.y * 32;
    int tx = threadIdx.x, ty = threadIdx.y;
    #pragma unroll
    for (int i = 0; i < 4; i++)
        tile[ty + i*8][tx] = y[((size_t)b*8192 + n0 + ty + i*8)*256 + c0 + tx];
    __syncthreads();
    #pragma unroll
    for (int i = 0; i < 4; i++)
        out[(size_t)b*2097152 + (size_t)(c0 + ty + i*8)*8192 + n0 + tx]
            = tile[tx][ty + i*8];
}

// ---------------------------------------------------------------------------
// Launch
// ---------------------------------------------------------------------------
static inline int attn_smem(int L) { return (L*36*2 + 32*L + L*(L+1)) * 4; }

extern "C" void kernel_launch(void* const* d_in, const int* in_sizes, int n_in,
                              void* d_out, int out_size)
{
    const float* src        = (const float*)d_in[0];
    const float* pos        = (const float*)d_in[1];
    const float* w_in_long  = (const float*)d_in[2];
    const float* b_in_long  = (const float*)d_in[3];
    const float* w_out_long = (const float*)d_in[4];
    const float* b_out_long = (const float*)d_in[5];
    const float* w_in_short = (const float*)d_in[6];
    const float* b_in_short = (const float*)d_in[7];
    const float* w_out_short= (const float*)d_in[8];
    const float* b_out_short= (const float*)d_in[9];
    const float* w1         = (const float*)d_in[10];
    const float* b1         = (const float*)d_in[11];
    const float* w2         = (const float*)d_in[12];
    const float* b2         = (const float*)d_in[13];
    const float* g1         = (const float*)d_in[14];
    const float* beta1      = (const float*)d_in[15];
    const float* g2         = (const float*)d_in[16];
    const float* beta2      = (const float*)d_in[17];
    float* out = (float*)d_out;

    static __half *p_xqk=nullptr,*p_xv,*p_q,*p_k,*p_v,*p_attn,*p_x16,*p_h;
    static __half *p_wl,*p_wol,*p_ws,*p_wos,*p_w1,*p_w2;
    static float  *p_mo,*p_x,*p_ff,*p_y;
    static bool init_done = false;
    if (!init_done) {
        cudaGetSymbolAddress((void**)&p_xqk , g_xqk );
        cudaGetSymbolAddress((void**)&p_xv  , g_xv  );
        cudaGetSymbolAddress((void**)&p_q   , g_q   );
        cudaGetSymbolAddress((void**)&p_k   , g_k   );
        cudaGetSymbolAddress((void**)&p_v   , g_v   );
        cudaGetSymbolAddress((void**)&p_attn, g_attn);
        cudaGetSymbolAddress((void**)&p_mo  , g_mo  );
        cudaGetSymbolAddress((void**)&p_x   , g_x   );
        cudaGetSymbolAddress((void**)&p_x16 , g_x16 );
        cudaGetSymbolAddress((void**)&p_ff  , g_ff  );
        cudaGetSymbolAddress((void**)&p_y   , g_y   );
        cudaGetSymbolAddress((void**)&p_h   , g_h   );
        cudaGetSymbolAddress((void**)&p_wl  , g_wl  );
        cudaGetSymbolAddress((void**)&p_wol , g_wol );
        cudaGetSymbolAddress((void**)&p_ws  , g_ws  );
        cudaGetSymbolAddress((void**)&p_wos , g_wos );
        cudaGetSymbolAddress((void**)&p_w1  , g_w1h );
        cudaGetSymbolAddress((void**)&p_w2  , g_w2h );
        cudaFuncSetAttribute(attn_kernel<64>,
            cudaFuncAttributeMaxDynamicSharedMemorySize, attn_smem(64));
        cudaFuncSetAttribute(attn_kernel<128>,
            cudaFuncAttributeMaxDynamicSharedMemorySize, attn_smem(128));
        cudaFuncSetAttribute((const void*)gemm_h<0,0>,
            cudaFuncAttributeMaxDynamicSharedMemorySize, GEMMH_SMEM);
        cudaFuncSetAttribute((const void*)gemm_h<1,1>,
            cudaFuncAttributeMaxDynamicSharedMemorySize, GEMMH_SMEM);
        cudaFuncSetAttribute((const void*)gemm_h<2,1>,
            cudaFuncAttributeMaxDynamicSharedMemorySize, GEMMH_SMEM);
        init_done = true;
    }

    // ---- weight conversion (fp32 -> fp16), every launch, deterministic ----
    f2h<<<768*256/1024, 256>>>(w_in_long,  p_wl,  768*256);
    f2h<<<256*256/1024, 256>>>(w_out_long, p_wol, 256*256);
    f2h<<<768*256/1024, 256>>>(w_in_short, p_ws,  768*256);
    f2h<<<256*256/1024, 256>>>(w_out_short,p_wos, 256*256);
    f2h<<<HID*256/1024, 256>>>(w1,         p_w1,  HID*256);
    f2h<<<256*HID/1024, 256>>>(w2,         p_w2,  256*HID);

    const dim3 gQKV(TOK/128, 6);
    const dim3 g256(TOK/128, 2);
    const dim3 gHID(TOK/128, 8);

    // ---- long-range MHA ----
    gather_long<<<TOK/4, 256>>>(src, pos, p_xqk, p_xv);
    gemm_h<2,1><<<gQKV, 256, GEMMH_SMEM>>>(p_xqk, p_xv, p_wl, b_in_long,
                                           p_q, p_k, p_v, TOK, 768, CDIM);
    attn_kernel<64><<<1024*8, 256, attn_smem(64)>>>(p_q, p_k, p_v, p_attn, 1024);
    gemm_h<0,0><<<g256, 256, GEMMH_SMEM>>>(p_attn, nullptr, p_wol, b_out_long,
                                           p_mo, nullptr, nullptr, TOK, CDIM, CDIM);

    // ---- short-range MHA ----
    gather_short<<<TOK/4, 256>>>(p_mo, pos, p_xqk, p_xv);
    gemm_h<2,1><<<gQKV, 256, GEMMH_SMEM>>>(p_xqk, p_xv, p_ws, b_in_short,
                                           p_q, p_k, p_v, TOK, 768, CDIM);
    attn_kernel<128><<<512*8, 256, attn_smem(128)>>>(p_q, p_k, p_v, p_attn, 512);
    gemm_h<0,0><<<g256, 256, GEMMH_SMEM>>>(p_attn, nullptr, p_wos, b_out_short,
                                           p_mo, nullptr, nullptr, TOK, CDIM, CDIM);

    // ---- residual + LN1 ----
    resid_ln1<<<TOK/8, 256>>>(src, p_mo, g1, beta1, p_x, p_x16);

    // ---- FFN ----
    gemm_h<1,1><<<gHID, 256, GEMMH_SMEM>>>(p_x16, nullptr, p_w1, b1,
                                           p_h, nullptr, nullptr, TOK, HID, CDIM);
    gemm_h<0,0><<<g256, 256, GEMMH_SMEM>>>(p_h, nullptr, p_w2, b2,
                                           p_ff, nullptr, nullptr, TOK, CDIM, HID);

    // ---- residual + LN2 ----
    add_ln<<<TOK/8, 256>>>(p_x, p_ff, g2, beta2, p_y);

    // ---- final layout reinterpretation ----
    transpose_out<<<dim3(8192/32, 256/32, 8), dim3(32, 8)>>>(p_y, out);
}

// round 7
// speedup vs baseline: 5.6487x; 1.9520x over previous
#include <cuda_runtime.h>
#include <cuda_fp16.h>
#include <cstdint>

#define TOK    65536
#define CDIM   256
#define HID    1024

// ---------------------------------------------------------------------------
// Scratch
// ---------------------------------------------------------------------------
__device__ __half g_xqk [TOK*CDIM];
__device__ __half g_xv  [TOK*CDIM];
__device__ __half g_q   [TOK*CDIM];
__device__ __half g_k   [TOK*CDIM];
__device__ __half g_v   [TOK*CDIM];
__device__ __half g_attn[TOK*CDIM];
__device__ __half g_mo16[TOK*CDIM];
__device__ float  g_x   [TOK*CDIM];
__device__ __half g_x16 [TOK*CDIM];
__device__ __half g_h   [TOK*HID];
__device__ float  g_ff  [TOK*CDIM];
// fp16 weights
__device__ __half g_wl [768*256];
__device__ __half g_wol[256*256];
__device__ __half g_ws [768*256];
__device__ __half g_wos[256*256];
__device__ __half g_w1h[HID*256];
__device__ __half g_w2h[256*HID];

// ---------------------------------------------------------------------------
// PTX helpers
// ---------------------------------------------------------------------------
__device__ __forceinline__ void cpasync16(uint32_t dst, const void* src) {
    asm volatile("cp.async.cg.shared.global [%0], [%1], 16;\n" :: "r"(dst), "l"(src));
}
__device__ __forceinline__ void cp_commit() {
    asm volatile("cp.async.commit_group;\n");
}
template<int N>
__device__ __forceinline__ void cp_wait() {
    asm volatile("cp.async.wait_group %0;\n" :: "n"(N));
}
__device__ __forceinline__ void ldsm4(uint32_t& r0, uint32_t& r1,
                                      uint32_t& r2, uint32_t& r3, uint32_t addr) {
    asm volatile("ldmatrix.sync.aligned.m8n8.x4.shared.b16 {%0,%1,%2,%3}, [%4];"
                 : "=r"(r0), "=r"(r1), "=r"(r2), "=r"(r3) : "r"(addr));
}
__device__ __forceinline__ void ldsm4t(uint32_t& r0, uint32_t& r1,
                                       uint32_t& r2, uint32_t& r3, uint32_t addr) {
    asm volatile("ldmatrix.sync.aligned.m8n8.x4.trans.shared.b16 {%0,%1,%2,%3}, [%4];"
                 : "=r"(r0), "=r"(r1), "=r"(r2), "=r"(r3) : "r"(addr));
}
__device__ __forceinline__ void mma16816(float c[4],
    uint32_t a0, uint32_t a1, uint32_t a2, uint32_t a3, uint32_t b0, uint32_t b1)
{
    asm volatile(
        "mma.sync.aligned.m16n8k16.row.col.f32.f16.f16.f32 "
        "{%0,%1,%2,%3}, {%4,%5,%6,%7}, {%8,%9}, {%0,%1,%2,%3};"
        : "+f"(c[0]), "+f"(c[1]), "+f"(c[2]), "+f"(c[3])
        : "r"(a0), "r"(a1), "r"(a2), "r"(a3), "r"(b0), "r"(b1));
}
__device__ __forceinline__ uint32_t pack2(float a, float b) {
    __half2 h = __floats2half2_rn(a, b);
    return *(uint32_t*)&h;
}

// ---------------------------------------------------------------------------
// FP16 tensor-core GEMM (same proven structure as R6)
// ---------------------------------------------------------------------------
#define STAGE_B 32768
#define GEMMH_SMEM (3*STAGE_B)

__device__ __forceinline__ void load_chunk16(const __half* __restrict__ A,
                                             const __half* __restrict__ B,
                                             int bm, int bn, int K, int kt,
                                             uint32_t sbase, int tid)
{
    #pragma unroll
    for (int j = 0; j < 4; j++) {
        int idx = tid*4 + j;
        int row = idx >> 3, c = idx & 7;
        uint32_t off = (uint32_t)(row*128 + ((c ^ (row & 7)) << 4));
        cpasync16(sbase + off, A + (size_t)(bm + row)*K + kt*64 + c*8);
    }
    #pragma unroll
    for (int j = 0; j < 4; j++) {
        int idx = tid*4 + j;
        int row = idx >> 3, c = idx & 7;
        uint32_t off = (uint32_t)(row*128 + ((c ^ (row & 7)) << 4));
        cpasync16(sbase + 16384 + off, B + (size_t)(bn + row)*K + kt*64 + c*8);
    }
    cp_commit();
}

template<int EPI, int OUTH>
__global__ void __launch_bounds__(256, 2)
gemm_h(const __half* __restrict__ A0, const __half* __restrict__ A1,
       const __half* __restrict__ B,  const float* __restrict__ bias,
       void* C0, void* C1, void* C2, int M, int N, int K)
{
    extern __shared__ __align__(128) char dsm[];
    const int tid = threadIdx.x;
    const int bm  = blockIdx.x * 128;
    const int bnG = blockIdx.y * 128;

    const __half* A = A0;
    if (EPI == 2) A = (blockIdx.y < 4) ? A0 : A1;

    uint32_t sb = (uint32_t)__cvta_generic_to_shared(dsm);

    const int lane = tid & 31, wid = tid >> 5;
    const int wm = (wid >> 2) * 64;
    const int wn = (wid & 3) * 32;
    const int lq = lane >> 3;
    const int l7 = lane & 7;

    float acc[4][4][4];
    #pragma unroll
    for (int mi = 0; mi < 4; mi++)
        #pragma unroll
        for (int ni = 0; ni < 4; ni++)
            #pragma unroll
            for (int r = 0; r < 4; r++) acc[mi][ni][r] = 0.f;

    const int KT = K / 64;

    load_chunk16(A, B, bm, bnG, K, 0, sb,           tid);
    load_chunk16(A, B, bm, bnG, K, 1, sb + STAGE_B, tid);

    int arow[4], brow[2];
    #pragma unroll
    for (int mi = 0; mi < 4; mi++) arow[mi] = wm + mi*16 + (lq & 1)*8 + l7;
    #pragma unroll
    for (int p = 0; p < 2; p++)    brow[p]  = wn + p*16 + (lq >> 1)*8 + l7;
    const int aqh = lq >> 1;
    const int bqh = lq & 1;

    for (int kt = 0; kt < KT; kt++) {
        if (kt + 2 < KT) cp_wait<1>(); else cp_wait<0>();
        __syncthreads();
        if (kt + 2 < KT)
            load_chunk16(A, B, bm, bnG, K, kt + 2,
                         sb + (uint32_t)((kt + 2) % 3)*STAGE_B, tid);

        uint32_t Ab = sb + (uint32_t)(kt % 3)*STAGE_B;
        uint32_t Bb = Ab + 16384;

        #pragma unroll
        for (int s = 0; s < 4; s++) {
            uint32_t af[4][4];
            #pragma unroll
            for (int mi = 0; mi < 4; mi++) {
                int row = arow[mi];
                uint32_t addr = Ab + (uint32_t)(row*128 +
                                (((2*s + aqh) ^ (row & 7)) << 4));
                ldsm4(af[mi][0], af[mi][1], af[mi][2], af[mi][3], addr);
            }
            uint32_t bf[4][2];
            #pragma unroll
            for (int p = 0; p < 2; p++) {
                int row = brow[p];
                uint32_t addr = Bb + (uint32_t)(row*128 +
                                (((2*s + bqh) ^ (row & 7)) << 4));
                ldsm4(bf[2*p][0], bf[2*p][1], bf[2*p+1][0], bf[2*p+1][1], addr);
            }
            #pragma unroll
            for (int mi = 0; mi < 4; mi++)
                #pragma unroll
                for (int ni = 0; ni < 4; ni++)
                    mma16816(acc[mi][ni], af[mi][0], af[mi][1], af[mi][2], af[mi][3],
                             bf[ni][0], bf[ni][1]);
        }
    }

    const int g2 = lane >> 2, t2 = lane & 3;
    void* dstp = C0;
    int ldc = N, colbase = bnG;
    if (EPI == 2) {
        int region = blockIdx.y >> 1;
        dstp = (region == 0) ? C0 : (region == 1 ? C1 : C2);
        ldc = 256;
        colbase = (blockIdx.y & 1) * 128;
    }

    #pragma unroll
    for (int mi = 0; mi < 4; mi++) {
        #pragma unroll
        for (int ni = 0; ni < 4; ni++) {
            int row = bm + wm + mi*16 + g2;
            int cg  = bnG + wn + ni*8 + t2*2;
            int cl  = colbase + wn + ni*8 + t2*2;
            float b0 = bias[cg], b1 = bias[cg + 1];
            float v0 = acc[mi][ni][0] + b0;
            float v1 = acc[mi][ni][1] + b1;
            float v2 = acc[mi][ni][2] + b0;
            float v3 = acc[mi][ni][3] + b1;
            if (EPI == 1) {
                v0 = fmaxf(v0, 0.f); v1 = fmaxf(v1, 0.f);
                v2 = fmaxf(v2, 0.f); v3 = fmaxf(v3, 0.f);
            }
            if (OUTH) {
                __half* d = (__half*)dstp;
                *(__half2*)&d[(size_t)row      *ldc + cl] = __floats2half2_rn(v0, v1);
                *(__half2*)&d[(size_t)(row + 8)*ldc + cl] = __floats2half2_rn(v2, v3);
            } else {
                float* d = (float*)dstp;
                *(float2*)&d[(size_t)row      *ldc + cl] = make_float2(v0, v1);
                *(float2*)&d[(size_t)(row + 8)*ldc + cl] = make_float2(v2, v3);
            }
        }
    }
}

// ---------------------------------------------------------------------------
// Single fused weight conversion (6 matrices, 1 launch, 1024 blocks)
// ---------------------------------------------------------------------------
__global__ void __launch_bounds__(256)
f2h_all(const float* __restrict__ wl, const float* __restrict__ wol,
        const float* __restrict__ ws, const float* __restrict__ wos,
        const float* __restrict__ w1, const float* __restrict__ w2)
{
    int blk = blockIdx.x;
    const float* s; __half* d;
    if      (blk < 192) { s = wl;  d = g_wl;              }
    else if (blk < 256) { s = wol; d = g_wol; blk -= 192; }
    else if (blk < 448) { s = ws;  d = g_ws;  blk -= 256; }
    else if (blk < 512) { s = wos; d = g_wos; blk -= 448; }
    else if (blk < 768) { s = w1;  d = g_w1h; blk -= 512; }
    else                { s = w2;  d = g_w2h; blk -= 768; }
    int i = (blk*256 + threadIdx.x) * 4;
    float4 v = *(const float4*)(s + i);
    uint2 o; o.x = pack2(v.x, v.y); o.y = pack2(v.z, v.w);
    *(uint2*)(d + i) = o;
}

// ---------------------------------------------------------------------------
// Tensor-core attention: flash-style, register-resident scores, exact softmax.
// One CTA per (batch-block, head); warp owns 16 query rows x all L keys.
// smem: Q,K,V fp16 swizzled (row = token, 64B = 32 halves).
// ---------------------------------------------------------------------------
template<int L>
__global__ void __launch_bounds__(2*L)
attn_tc(const __half* __restrict__ Q, const __half* __restrict__ K,
        const __half* __restrict__ V, __half* __restrict__ O, int BtC)
{
    __shared__ __align__(128) __half sQ[L*32];
    __shared__ __align__(128) __half sK[L*32];
    __shared__ __align__(128) __half sV[L*32];

    const int bt   = blockIdx.x % BtC;
    const int h    = blockIdx.x / BtC;
    const int tid  = threadIdx.x;
    const int lane = tid & 31, w = tid >> 5;
    const float scale = 0.17677669529663687f;   // 1/sqrt(32)

    uint32_t bq = (uint32_t)__cvta_generic_to_shared(sQ);
    uint32_t bk = (uint32_t)__cvta_generic_to_shared(sK);
    uint32_t bv = (uint32_t)__cvta_generic_to_shared(sV);

    // ---- async load Q,K,V (16B segments, XOR-swizzled) ----
    for (int seg = tid; seg < L*4; seg += 2*L) {
        int l = seg >> 2, u = seg & 3;
        size_t g = ((size_t)l * BtC + bt) * 256 + h*32 + u*8;
        uint32_t so = (uint32_t)(l*64 + ((u ^ (l & 3)) << 4));
        cpasync16(bq + so, Q + g);
        cpasync16(bk + so, K + g);
        cpasync16(bv + so, V + g);
    }
    cp_commit();
    cp_wait<0>();
    __syncthreads();

    // ---- scores S = Q K^T (warp rows 16w..16w+15, accum in regs) ----
    float sa[L/8][4];
    #pragma unroll
    for (int ni = 0; ni < L/8; ni++)
        #pragma unroll
        for (int r = 0; r < 4; r++) sa[ni][r] = 0.f;

    uint32_t a[2][4];
    {
        int arow = w*16 + (lane & 15);
        uint32_t ab = bq + (uint32_t)(arow*64);
        #pragma unroll
        for (int s = 0; s < 2; s++) {
            uint32_t addr = ab + (uint32_t)(((((lane>>4) + 2*s) ^ (arow & 3)) << 4));
            ldsm4(a[s][0], a[s][1], a[s][2], a[s][3], addr);
        }
    }
    {
        int br7 = (lane & 7) + ((lane >> 4) << 3);
        int bu  = (lane >> 3) & 1;
        #pragma unroll
        for (int j = 0; j < L/16; j++) {
            int row = j*16 + br7;
            uint32_t rb = bk + (uint32_t)(row*64);
            #pragma unroll
            for (int s = 0; s < 2; s++) {
                uint32_t addr = rb + (uint32_t)((((bu + 2*s) ^ (row & 3)) << 4));
                uint32_t b0, b1, b2, b3;
                ldsm4(b0, b1, b2, b3, addr);
                mma16816(sa[2*j],   a[s][0], a[s][1], a[s][2], a[s][3], b0, b1);
                mma16816(sa[2*j+1], a[s][0], a[s][1], a[s][2], a[s][3], b2, b3);
            }
        }
    }

    // ---- exact softmax per row (row = quad; cols spread over ni,t) ----
    float mlo = -1e30f, mhi = -1e30f;
    #pragma unroll
    for (int ni = 0; ni < L/8; ni++) {
        mlo = fmaxf(mlo, fmaxf(sa[ni][0], sa[ni][1]));
        mhi = fmaxf(mhi, fmaxf(sa[ni][2], sa[ni][3]));
    }
    #pragma unroll
    for (int o = 1; o <= 2; o <<= 1) {
        mlo = fmaxf(mlo, __shfl_xor_sync(~0u, mlo, o));
        mhi = fmaxf(mhi, __shfl_xor_sync(~0u, mhi, o));
    }
    float slo = 0.f, shi = 0.f;
    #pragma unroll
    for (int ni = 0; ni < L/8; ni++) {
        float e0 = __expf((sa[ni][0] - mlo) * scale);
        float e1 = __expf((sa[ni][1] - mlo) * scale);
        float e2 = __expf((sa[ni][2] - mhi) * scale);
        float e3 = __expf((sa[ni][3] - mhi) * scale);
        sa[ni][0] = e0; sa[ni][1] = e1; sa[ni][2] = e2; sa[ni][3] = e3;
        slo += e0 + e1; shi += e2 + e3;
    }
    #pragma unroll
    for (int o = 1; o <= 2; o <<= 1) {
        slo += __shfl_xor_sync(~0u, slo, o);
        shi += __shfl_xor_sync(~0u, shi, o);
    }
    const float ilo = 1.f / slo, ihi = 1.f / shi;

    // ---- O = P V (P re-packed from accumulators; V via ldmatrix.trans) ----
    float oa[4][4];
    #pragma unroll
    for (int ni = 0; ni < 4; ni++)
        #pragma unroll
        for (int r = 0; r < 4; r++) oa[ni][r] = 0.f;

    {
        int vr7 = (lane & 7) + (((lane >> 3) & 1) << 3);
        int vu  = lane >> 4;
        #pragma unroll
        for (int s = 0; s < L/16; s++) {
            int row = s*16 + vr7;
            uint32_t rb = bv + (uint32_t)(row*64);
            uint32_t v0,v1,v2,v3,v4,v5,v6,v7;
            ldsm4t(v0, v1, v2, v3, rb + (uint32_t)(((vu       ^ (row & 3)) << 4)));
            ldsm4t(v4, v5, v6, v7, rb + (uint32_t)((((vu + 2) ^ (row & 3)) << 4)));
            uint32_t a0 = pack2(sa[2*s  ][0], sa[2*s  ][1]);
            uint32_t a1 = pack2(sa[2*s  ][2], sa[2*s  ][3]);
            uint32_t a2 = pack2(sa[2*s+1][0], sa[2*s+1][1]);
            uint32_t a3 = pack2(sa[2*s+1][2], sa[2*s+1][3]);
            mma16816(oa[0], a0, a1, a2, a3, v0, v1);
            mma16816(oa[1], a0, a1, a2, a3, v2, v3);
            mma16816(oa[2], a0, a1, a2, a3, v4, v5);
            mma16816(oa[3], a0, a1, a2, a3, v6, v7);
        }
    }

    // ---- normalize & store ----
    {
        int g2 = lane >> 2, t2 = (lane & 3) * 2;
        int rlo = w*16 + g2, rhi = rlo + 8;
        size_t glo = ((size_t)rlo * BtC + bt) * 256 + h*32 + t2;
        size_t ghi = ((size_t)rhi * BtC + bt) * 256 + h*32 + t2;
        #pragma unroll
        for (int ni = 0; ni < 4; ni++) {
            *(__half2*)&O[glo + ni*8] = __floats2half2_rn(oa[ni][0]*ilo, oa[ni][1]*ilo);
            *(__half2*)&O[ghi + ni*8] = __floats2half2_rn(oa[ni][2]*ihi, oa[ni][3]*ihi);
        }
    }
}

// ---------------------------------------------------------------------------
// Gathers
// ---------------------------------------------------------------------------
__global__ void __launch_bounds__(256)
gather_long(const float* __restrict__ src, const float* __restrict__ pos,
            __half* __restrict__ xqk, __half* __restrict__ xv)
{
    int t  = blockIdx.x * 4 + (threadIdx.x >> 6);
    int c4 = (threadIdx.x & 63) * 4;
    int Lc = t >> 10, Bt = t & 1023;
    int bh = Lc >> 3, w = Lc & 7;
    int b  = Bt >> 7, hh = (Bt >> 3) & 15, ww = Bt & 7;
    int n  = bh*1024 + hh*64 + w*8 + ww;
    float4 s4 = *(const float4*)(src + ((size_t)b*8192 + n)*256 + c4);
    float4 p4 = *(const float4*)(pos + (size_t)n*256 + c4);
    uint2 ov; ov.x = pack2(s4.x, s4.y); ov.y = pack2(s4.z, s4.w);
    *(uint2*)(xv + (size_t)t*256 + c4) = ov;
    uint2 oq; oq.x = pack2(s4.x+p4.x, s4.y+p4.y); oq.y = pack2(s4.z+p4.z, s4.w+p4.w);
    *(uint2*)(xqk + (size_t)t*256 + c4) = oq;
}

__global__ void __launch_bounds__(256)
gather_short(const __half* __restrict__ mo, const float* __restrict__ pos,
             __half* __restrict__ xqk, __half* __restrict__ xv)
{
    int ts = blockIdx.x * 4 + (threadIdx.x >> 6);
    int c4 = (threadIdx.x & 63) * 4;
    int Ls = ts >> 9, Bts = ts & 511;
    int h2 = Ls >> 3, ww2 = Ls & 7;
    int b2 = Bts >> 6, bh2 = (Bts >> 3) & 7, w2 = Bts & 7;
    int f  = b2*8192 + bh2*1024 + h2*64 + w2*8 + ww2;
    int Lf = f >> 10, r = f & 1023;
    int bh = Lf >> 3, w = Lf & 7, hh = (r >> 3) & 15, ww = r & 7;
    int n  = bh*1024 + hh*64 + w*8 + ww;
    uint2 mraw = *(const uint2*)(mo + (size_t)f*256 + c4);
    __half2 m01 = *(__half2*)&mraw.x, m23 = *(__half2*)&mraw.y;
    float2 f01 = __half22float2(m01), f23 = __half22float2(m23);
    float4 p4 = *(const float4*)(pos + (size_t)n*256 + c4);
    *(uint2*)(xv + (size_t)ts*256 + c4) = mraw;
    uint2 oq;
    oq.x = pack2(f01.x + p4.x, f01.y + p4.y);
    oq.y = pack2(f23.x + p4.z, f23.y + p4.w);
    *(uint2*)(xqk + (size_t)ts*256 + c4) = oq;
}

// ---------------------------------------------------------------------------
// Residual + scatter + LayerNorm1 (fp16 mo input; fp32 + fp16 outputs)
// ---------------------------------------------------------------------------
__global__ void __launch_bounds__(256)
resid_ln1(const float* __restrict__ src, const __half* __restrict__ mo,
          const float* __restrict__ g, const float* __restrict__ be,
          float* __restrict__ out, __half* __restrict__ out16)
{
    int tok  = blockIdx.x * 8 + (threadIdx.x >> 5);
    int lane = threadIdx.x & 31;
    int b = tok >> 13, n = tok & 8191;
    int h2 = n >> 9, bh2 = (n >> 6) & 7, ww2 = (n >> 3) & 7, w2 = n & 7;
    int ts = (h2*8 + ww2)*512 + b*64 + bh2*8 + w2;
    const float*  xs = src + (size_t)tok*256;
    const __half* ms = mo  + (size_t)ts *256;
    float v[8], sum = 0.f, sq = 0.f;
    #pragma unroll
    for (int i = 0; i < 8; i++) {
        float x = xs[lane + 32*i] + __half2float(ms[lane + 32*i]);
        v[i] = x; sum += x; sq += x*x;
    }
    #pragma unroll
    for (int o = 16; o; o >>= 1) {
        sum += __shfl_xor_sync(~0u, sum, o);
        sq  += __shfl_xor_sync(~0u, sq , o);
    }
    float mu  = sum * (1.f/256.f);
    float var = sq * (1.f/256.f) - mu*mu;
    float inv = rsqrtf(var + 1e-5f);
    #pragma unroll
    for (int i = 0; i < 8; i++) {
        int c = lane + 32*i;
        float r = (v[i] - mu) * inv * g[c] + be[c];
        out  [(size_t)tok*256 + c] = r;
        out16[(size_t)tok*256 + c] = __float2half(r);
    }
}

// ---------------------------------------------------------------------------
// Fused residual + LayerNorm2 + output transpose ([B,N,C] -> [B,C,N] flat)
// Block: 32 tokens x 256 channels; 8 warps (4 tokens each), then transposed
// coalesced writes through padded smem.
// ---------------------------------------------------------------------------
__global__ void __launch_bounds__(256)
add_ln_tr(const float* __restrict__ a, const float* __restrict__ bsrc,
          const float* __restrict__ g, const float* __restrict__ be,
          float* __restrict__ out)
{
    __shared__ float tile[32][257];
    int blk = blockIdx.x;
    int b = blk >> 8, nb = blk & 255;
    int n0 = nb * 32;
    int w = threadIdx.x >> 5, lane = threadIdx.x & 31;

    #pragma unroll
    for (int i = 0; i < 4; i++) {
        int lt = w*4 + i;
        size_t tok = (size_t)b*8192 + n0 + lt;
        const float* xa = a    + tok*256;
        const float* xb = bsrc + tok*256;
        float v[8], sum = 0.f, sq = 0.f;
        #pragma unroll
        for (int e = 0; e < 8; e++) {
            float x = xa[lane + 32*e] + xb[lane + 32*e];
            v[e] = x; sum += x; sq += x*x;
        }
        #pragma unroll
        for (int o = 16; o; o >>= 1) {
            sum += __shfl_xor_sync(~0u, sum, o);
            sq  += __shfl_xor_sync(~0u, sq , o);
        }
        float mu  = sum * (1.f/256.f);
        float var = sq * (1.f/256.f) - mu*mu;
        float inv = rsqrtf(var + 1e-5f);
        #pragma unroll
        for (int e = 0; e < 8; e++) {
            int c = lane + 32*e;
            tile[lt][c] = (v[e] - mu) * inv * g[c] + be[c];
        }
    }
    __syncthreads();

    size_t ob = (size_t)b*2097152 + n0 + lane;
    #pragma unroll
    for (int k = 0; k < 32; k++) {
        int c = w*32 + k;
        out[ob + (size_t)c*8192] = tile[lane][c];
    }
}

// ---------------------------------------------------------------------------
// Launch
// ---------------------------------------------------------------------------
extern "C" void kernel_launch(void* const* d_in, const int* in_sizes, int n_in,
                              void* d_out, int out_size)
{
    const float* src        = (const float*)d_in[0];
    const float* pos        = (const float*)d_in[1];
    const float* w_in_long  = (const float*)d_in[2];
    const float* b_in_long  = (const float*)d_in[3];
    const float* w_out_long = (const float*)d_in[4];
    const float* b_out_long = (const float*)d_in[5];
    const float* w_in_short = (const float*)d_in[6];
    const float* b_in_short = (const float*)d_in[7];
    const float* w_out_short= (const float*)d_in[8];
    const float* b_out_short= (const float*)d_in[9];
    const float* w1         = (const float*)d_in[10];
    const float* b1         = (const float*)d_in[11];
    const float* w2         = (const float*)d_in[12];
    const float* b2         = (const float*)d_in[13];
    const float* g1         = (const float*)d_in[14];
    const float* beta1      = (const float*)d_in[15];
    const float* g2         = (const float*)d_in[16];
    const float* beta2      = (const float*)d_in[17];
    float* out = (float*)d_out;

    static __half *p_xqk=nullptr,*p_xv,*p_q,*p_k,*p_v,*p_attn,*p_mo16,*p_x16,*p_h;
    static __half *p_wl,*p_wol,*p_ws,*p_wos,*p_w1,*p_w2;
    static float  *p_x,*p_ff;
    static bool init_done = false;
    if (!init_done) {
        cudaGetSymbolAddress((void**)&p_xqk , g_xqk );
        cudaGetSymbolAddress((void**)&p_xv  , g_xv  );
        cudaGetSymbolAddress((void**)&p_q   , g_q   );
        cudaGetSymbolAddress((void**)&p_k   , g_k   );
        cudaGetSymbolAddress((void**)&p_v   , g_v   );
        cudaGetSymbolAddress((void**)&p_attn, g_attn);
        cudaGetSymbolAddress((void**)&p_mo16, g_mo16);
        cudaGetSymbolAddress((void**)&p_x   , g_x   );
        cudaGetSymbolAddress((void**)&p_x16 , g_x16 );
        cudaGetSymbolAddress((void**)&p_ff  , g_ff  );
        cudaGetSymbolAddress((void**)&p_h   , g_h   );
        cudaGetSymbolAddress((void**)&p_wl  , g_wl  );
        cudaGetSymbolAddress((void**)&p_wol , g_wol );
        cudaGetSymbolAddress((void**)&p_ws  , g_ws  );
        cudaGetSymbolAddress((void**)&p_wos , g_wos );
        cudaGetSymbolAddress((void**)&p_w1  , g_w1h );
        cudaGetSymbolAddress((void**)&p_w2  , g_w2h );
        cudaFuncSetAttribute((const void*)gemm_h<0,0>,
            cudaFuncAttributeMaxDynamicSharedMemorySize, GEMMH_SMEM);
        cudaFuncSetAttribute((const void*)gemm_h<0,1>,
            cudaFuncAttributeMaxDynamicSharedMemorySize, GEMMH_SMEM);
        cudaFuncSetAttribute((const void*)gemm_h<1,1>,
            cudaFuncAttributeMaxDynamicSharedMemorySize, GEMMH_SMEM);
        cudaFuncSetAttribute((const void*)gemm_h<2,1>,
            cudaFuncAttributeMaxDynamicSharedMemorySize, GEMMH_SMEM);
        init_done = true;
    }

    // ---- weight conversion: single launch ----
    f2h_all<<<1024, 256>>>(w_in_long, w_out_long, w_in_short, w_out_short, w1, w2);

    const dim3 gQKV(TOK/128, 6);
    const dim3 g256(TOK/128, 2);
    const dim3 gHID(TOK/128, 8);

    // ---- long-range MHA ----
    gather_long<<<TOK/4, 256>>>(src, pos, p_xqk, p_xv);
    gemm_h<2,1><<<gQKV, 256, GEMMH_SMEM>>>(p_xqk, p_xv, p_wl, b_in_long,
                                           p_q, p_k, p_v, TOK, 768, CDIM);
    attn_tc<64><<<1024*8, 128>>>(p_q, p_k, p_v, p_attn, 1024);
    gemm_h<0,1><<<g256, 256, GEMMH_SMEM>>>(p_attn, nullptr, p_wol, b_out_long,
                                           p_mo16, nullptr, nullptr, TOK, CDIM, CDIM);

    // ---- short-range MHA ----
    gather_short<<<TOK/4, 256>>>(p_mo16, pos, p_xqk, p_xv);
    gemm_h<2,1><<<gQKV, 256, GEMMH_SMEM>>>(p_xqk, p_xv, p_ws, b_in_short,
                                           p_q, p_k, p_v, TOK, 768, CDIM);
    attn_tc<128><<<512*8, 256>>>(p_q, p_k, p_v, p_attn, 512);
    gemm_h<0,1><<<g256, 256, GEMMH_SMEM>>>(p_attn, nullptr, p_wos, b_out_short,
                                           p_mo16, nullptr, nullptr, TOK, CDIM, CDIM);

    // ---- residual + LN1 ----
    resid_ln1<<<TOK/8, 256>>>(src, p_mo16, g1, beta1, p_x, p_x16);

    // ---- FFN ----
    gemm_h<1,1><<<gHID, 256, GEMMH_SMEM>>>(p_x16, nullptr, p_w1, b1,
                                           p_h, nullptr, nullptr, TOK, HID, CDIM);
    gemm_h<0,0><<<g256, 256, GEMMH_SMEM>>>(p_h, nullptr, p_w2, b2,
                                           p_ff, nullptr, nullptr, TOK, CDIM, HID);

    // ---- residual + LN2 + output transpose (fused) ----
    add_ln_tr<<<2048, 256>>>(p_x, p_ff, g2, beta2, out);
}

// round 8
// speedup vs baseline: 5.6528x; 1.0007x over previous
#include <cuda_runtime.h>
#include <cuda_fp16.h>
#include <cstdint>

#define TOK    65536
#define CDIM   256
#define HID    1024

// ---------------------------------------------------------------------------
// Scratch
// ---------------------------------------------------------------------------
__device__ __half g_xqk [TOK*CDIM];
__device__ __half g_xv  [TOK*CDIM];
__device__ __half g_q   [TOK*CDIM];
__device__ __half g_k   [TOK*CDIM];
__device__ __half g_v   [TOK*CDIM];
__device__ __half g_attn[TOK*CDIM];
__device__ __half g_mo16[TOK*CDIM];
__device__ float  g_x   [TOK*CDIM];
__device__ __half g_x16 [TOK*CDIM];
__device__ __half g_h   [TOK*HID];
__device__ float  g_ff  [TOK*CDIM];
// fp16 weights
__device__ __half g_wl [768*256];
__device__ __half g_wol[256*256];
__device__ __half g_ws [768*256];
__device__ __half g_wos[256*256];
__device__ __half g_w1h[HID*256];
__device__ __half g_w2h[256*HID];

// ---------------------------------------------------------------------------
// PTX helpers
// ---------------------------------------------------------------------------
__device__ __forceinline__ void cpasync16(uint32_t dst, const void* src) {
    asm volatile("cp.async.cg.shared.global [%0], [%1], 16;\n" :: "r"(dst), "l"(src));
}
__device__ __forceinline__ void cp_commit() {
    asm volatile("cp.async.commit_group;\n");
}
template<int N>
__device__ __forceinline__ void cp_wait() {
    asm volatile("cp.async.wait_group %0;\n" :: "n"(N));
}
__device__ __forceinline__ void ldsm4(uint32_t& r0, uint32_t& r1,
                                      uint32_t& r2, uint32_t& r3, uint32_t addr) {
    asm volatile("ldmatrix.sync.aligned.m8n8.x4.shared.b16 {%0,%1,%2,%3}, [%4];"
                 : "=r"(r0), "=r"(r1), "=r"(r2), "=r"(r3) : "r"(addr));
}
__device__ __forceinline__ void ldsm4t(uint32_t& r0, uint32_t& r1,
                                       uint32_t& r2, uint32_t& r3, uint32_t addr) {
    asm volatile("ldmatrix.sync.aligned.m8n8.x4.trans.shared.b16 {%0,%1,%2,%3}, [%4];"
                 : "=r"(r0), "=r"(r1), "=r"(r2), "=r"(r3) : "r"(addr));
}
__device__ __forceinline__ void mma16816(float c[4],
    uint32_t a0, uint32_t a1, uint32_t a2, uint32_t a3, uint32_t b0, uint32_t b1)
{
    asm volatile(
        "mma.sync.aligned.m16n8k16.row.col.f32.f16.f16.f32 "
        "{%0,%1,%2,%3}, {%4,%5,%6,%7}, {%8,%9}, {%0,%1,%2,%3};"
        : "+f"(c[0]), "+f"(c[1]), "+f"(c[2]), "+f"(c[3])
        : "r"(a0), "r"(a1), "r"(a2), "r"(a3), "r"(b0), "r"(b1));
}
__device__ __forceinline__ uint32_t pack2(float a, float b) {
    __half2 h = __floats2half2_rn(a, b);
    return *(uint32_t*)&h;
}

// short-layout permutation: long-flat token f -> (short token ts, pos index n)
__device__ __forceinline__ void fmap_short(int f, int& ts, int& n) {
    int b2 = f >> 13, bh2 = (f >> 10) & 7, h2 = (f >> 6) & 15;
    int w2 = (f >> 3) & 7, ww2 = f & 7;
    ts = (h2*8 + ww2)*512 + b2*64 + bh2*8 + w2;
    int Lf = f >> 10, r = f & 1023;
    int bh = Lf >> 3, w = Lf & 7, hh = (r >> 3) & 15, ww = r & 7;
    n = bh*1024 + hh*64 + w*8 + ww;
}

// ---------------------------------------------------------------------------
// FP16 tensor-core GEMM
// EPI: 0 plain, 1 ReLU, 2 fused-QKV split, 3 fused short-gather scatter
// OUTH: 1 fp16 C, 0 fp32 C
// ---------------------------------------------------------------------------
#define STAGE_B 32768
#define GEMMH_SMEM (3*STAGE_B)

__device__ __forceinline__ void load_chunk16(const __half* __restrict__ A,
                                             const __half* __restrict__ B,
                                             int bm, int bn, int K, int kt,
                                             uint32_t sbase, int tid)
{
    #pragma unroll
    for (int j = 0; j < 4; j++) {
        int idx = tid*4 + j;
        int row = idx >> 3, c = idx & 7;
        uint32_t off = (uint32_t)(row*128 + ((c ^ (row & 7)) << 4));
        cpasync16(sbase + off, A + (size_t)(bm + row)*K + kt*64 + c*8);
    }
    #pragma unroll
    for (int j = 0; j < 4; j++) {
        int idx = tid*4 + j;
        int row = idx >> 3, c = idx & 7;
        uint32_t off = (uint32_t)(row*128 + ((c ^ (row & 7)) << 4));
        cpasync16(sbase + 16384 + off, B + (size_t)(bn + row)*K + kt*64 + c*8);
    }
    cp_commit();
}

template<int EPI, int OUTH>
__global__ void __launch_bounds__(256, 2)
gemm_h(const __half* __restrict__ A0, const __half* __restrict__ A1,
       const __half* __restrict__ B,  const float* __restrict__ bias,
       const float* __restrict__ pos,
       void* C0, void* C1, void* C2, int M, int N, int K)
{
    extern __shared__ __align__(128) char dsm[];
    const int tid = threadIdx.x;
    const int bm  = blockIdx.x * 128;
    const int bnG = blockIdx.y * 128;

    const __half* A = A0;
    if (EPI == 2) A = (blockIdx.y < 4) ? A0 : A1;

    uint32_t sb = (uint32_t)__cvta_generic_to_shared(dsm);

    const int lane = tid & 31, wid = tid >> 5;
    const int wm = (wid >> 2) * 64;
    const int wn = (wid & 3) * 32;
    const int lq = lane >> 3;
    const int l7 = lane & 7;

    float acc[4][4][4];
    #pragma unroll
    for (int mi = 0; mi < 4; mi++)
        #pragma unroll
        for (int ni = 0; ni < 4; ni++)
            #pragma unroll
            for (int r = 0; r < 4; r++) acc[mi][ni][r] = 0.f;

    const int KT = K / 64;

    load_chunk16(A, B, bm, bnG, K, 0, sb,           tid);
    load_chunk16(A, B, bm, bnG, K, 1, sb + STAGE_B, tid);

    int arow[4], brow[2];
    #pragma unroll
    for (int mi = 0; mi < 4; mi++) arow[mi] = wm + mi*16 + (lq & 1)*8 + l7;
    #pragma unroll
    for (int p = 0; p < 2; p++)    brow[p]  = wn + p*16 + (lq >> 1)*8 + l7;
    const int aqh = lq >> 1;
    const int bqh = lq & 1;

    for (int kt = 0; kt < KT; kt++) {
        if (kt + 2 < KT) cp_wait<1>(); else cp_wait<0>();
        __syncthreads();
        if (kt + 2 < KT)
            load_chunk16(A, B, bm, bnG, K, kt + 2,
                         sb + (uint32_t)((kt + 2) % 3)*STAGE_B, tid);

        uint32_t Ab = sb + (uint32_t)(kt % 3)*STAGE_B;
        uint32_t Bb = Ab + 16384;

        #pragma unroll
        for (int s = 0; s < 4; s++) {
            uint32_t af[4][4];
            #pragma unroll
            for (int mi = 0; mi < 4; mi++) {
                int row = arow[mi];
                uint32_t addr = Ab + (uint32_t)(row*128 +
                                (((2*s + aqh) ^ (row & 7)) << 4));
                ldsm4(af[mi][0], af[mi][1], af[mi][2], af[mi][3], addr);
            }
            uint32_t bf[4][2];
            #pragma unroll
            for (int p = 0; p < 2; p++) {
                int row = brow[p];
                uint32_t addr = Bb + (uint32_t)(row*128 +
                                (((2*s + bqh) ^ (row & 7)) << 4));
                ldsm4(bf[2*p][0], bf[2*p][1], bf[2*p+1][0], bf[2*p+1][1], addr);
            }
            #pragma unroll
            for (int mi = 0; mi < 4; mi++)
                #pragma unroll
                for (int ni = 0; ni < 4; ni++)
                    mma16816(acc[mi][ni], af[mi][0], af[mi][1], af[mi][2], af[mi][3],
                             bf[ni][0], bf[ni][1]);
        }
    }

    const int g2 = lane >> 2, t2 = lane & 3;

    if (EPI == 3) {
        // fused short-gather scatter: rows are long-flat tokens f;
        // write xv[ts]=v, xqk[ts]=v+pos[n]
        __half* xqk = (__half*)C0;
        __half* xv  = (__half*)C1;
        #pragma unroll
        for (int mi = 0; mi < 4; mi++) {
            int f0 = bm + wm + mi*16 + g2;
            int f1 = f0 + 8;
            int ts0, n0, ts1, n1;
            fmap_short(f0, ts0, n0);
            fmap_short(f1, ts1, n1);
            #pragma unroll
            for (int ni = 0; ni < 4; ni++) {
                int cg = bnG + wn + ni*8 + t2*2;
                float b0 = bias[cg], b1 = bias[cg + 1];
                float v0 = acc[mi][ni][0] + b0;
                float v1 = acc[mi][ni][1] + b1;
                float v2 = acc[mi][ni][2] + b0;
                float v3 = acc[mi][ni][3] + b1;
                float2 p0 = *(const float2*)&pos[(size_t)n0*256 + cg];
                float2 p1 = *(const float2*)&pos[(size_t)n1*256 + cg];
                *(__half2*)&xv [(size_t)ts0*256 + cg] = __floats2half2_rn(v0, v1);
                *(__half2*)&xv [(size_t)ts1*256 + cg] = __floats2half2_rn(v2, v3);
                *(__half2*)&xqk[(size_t)ts0*256 + cg] = __floats2half2_rn(v0+p0.x, v1+p0.y);
                *(__half2*)&xqk[(size_t)ts1*256 + cg] = __floats2half2_rn(v2+p1.x, v3+p1.y);
            }
        }
        return;
    }

    void* dstp = C0;
    int ldc = N, colbase = bnG;
    if (EPI == 2) {
        int region = blockIdx.y >> 1;
        dstp = (region == 0) ? C0 : (region == 1 ? C1 : C2);
        ldc = 256;
        colbase = (blockIdx.y & 1) * 128;
    }

    #pragma unroll
    for (int mi = 0; mi < 4; mi++) {
        #pragma unroll
        for (int ni = 0; ni < 4; ni++) {
            int row = bm + wm + mi*16 + g2;
            int cg  = bnG + wn + ni*8 + t2*2;
            int cl  = colbase + wn + ni*8 + t2*2;
            float b0 = bias[cg], b1 = bias[cg + 1];
            float v0 = acc[mi][ni][0] + b0;
            float v1 = acc[mi][ni][1] + b1;
            float v2 = acc[mi][ni][2] + b0;
            float v3 = acc[mi][ni][3] + b1;
            if (EPI == 1) {
                v0 = fmaxf(v0, 0.f); v1 = fmaxf(v1, 0.f);
                v2 = fmaxf(v2, 0.f); v3 = fmaxf(v3, 0.f);
            }
            if (OUTH) {
                __half* d = (__half*)dstp;
                *(__half2*)&d[(size_t)row      *ldc + cl] = __floats2half2_rn(v0, v1);
                *(__half2*)&d[(size_t)(row + 8)*ldc + cl] = __floats2half2_rn(v2, v3);
            } else {
                float* d = (float*)dstp;
                *(float2*)&d[(size_t)row      *ldc + cl] = make_float2(v0, v1);
                *(float2*)&d[(size_t)(row + 8)*ldc + cl] = make_float2(v2, v3);
            }
        }
    }
}

// ---------------------------------------------------------------------------
// Single fused weight conversion
// ---------------------------------------------------------------------------
__global__ void __launch_bounds__(256)
f2h_all(const float* __restrict__ wl, const float* __restrict__ wol,
        const float* __restrict__ ws, const float* __restrict__ wos,
        const float* __restrict__ w1, const float* __restrict__ w2)
{
    int blk = blockIdx.x;
    const float* s; __half* d;
    if      (blk < 192) { s = wl;  d = g_wl;              }
    else if (blk < 256) { s = wol; d = g_wol; blk -= 192; }
    else if (blk < 448) { s = ws;  d = g_ws;  blk -= 256; }
    else if (blk < 512) { s = wos; d = g_wos; blk -= 448; }
    else if (blk < 768) { s = w1;  d = g_w1h; blk -= 512; }
    else                { s = w2;  d = g_w2h; blk -= 768; }
    int i = (blk*256 + threadIdx.x) * 4;
    float4 v = *(const float4*)(s + i);
    uint2 o; o.x = pack2(v.x, v.y); o.y = pack2(v.z, v.w);
    *(uint2*)(d + i) = o;
}

// ---------------------------------------------------------------------------
// Tensor-core attention, TWO heads per CTA (full 128B-line coalescing).
// CTA = head-pair hp x batch-block bt. Warp group per head; warp owns 16 rows.
// smem rows: token -> 128 bytes (two heads x 64B), XOR-swizzled in 16B units.
// ---------------------------------------------------------------------------
template<int L>
__global__ void __launch_bounds__(4*L)
attn_tc2(const __half* __restrict__ Q, const __half* __restrict__ K,
         const __half* __restrict__ V, __half* __restrict__ O, int BtC)
{
    constexpr int WPH = L/16;
    __shared__ __align__(128) __half sQ[L*64];
    __shared__ __align__(128) __half sK[L*64];
    __shared__ __align__(128) __half sV[L*64];

    const int bt   = blockIdx.x % BtC;
    const int hp   = blockIdx.x / BtC;        // head pair 0..3
    const int tid  = threadIdx.x;
    const int lane = tid & 31, w = tid >> 5;
    const int hh   = w / WPH;                 // head in pair (0/1)
    const int wi   = w % WPH;                 // warp within head
    const float scale = 0.17677669529663687f;

    uint32_t bq = (uint32_t)__cvta_generic_to_shared(sQ);
    uint32_t bk = (uint32_t)__cvta_generic_to_shared(sK);
    uint32_t bv = (uint32_t)__cvta_generic_to_shared(sV);

    // ---- async load Q,K,V: 128B contiguous per token ----
    #pragma unroll
    for (int seg = tid; seg < L*8; seg += 4*L) {
        int l = seg >> 3, u = seg & 7;
        size_t g = ((size_t)l * BtC + bt) * 256 + hp*64 + u*8;
        uint32_t so = (uint32_t)(l*128 + ((u ^ (l & 7)) << 4));
        cpasync16(bq + so, Q + g);
        cpasync16(bk + so, K + g);
        cpasync16(bv + so, V + g);
    }
    cp_commit();
    cp_wait<0>();
    __syncthreads();

    // ---- scores S = Q K^T ----
    float sa[L/8][4];
    #pragma unroll
    for (int ni = 0; ni < L/8; ni++)
        #pragma unroll
        for (int r = 0; r < 4; r++) sa[ni][r] = 0.f;

    uint32_t a[2][4];
    {
        int arow = wi*16 + (lane & 15);
        uint32_t ab = bq + (uint32_t)(arow*128);
        #pragma unroll
        for (int s = 0; s < 2; s++) {
            int unit = hh*4 + 2*s + (lane >> 4);
            ldsm4(a[s][0], a[s][1], a[s][2], a[s][3],
                  ab + (uint32_t)((unit ^ (arow & 7)) << 4));
        }
    }
    {
        int br7 = (lane & 7) + ((lane >> 4) << 3);
        int bu  = (lane >> 3) & 1;
        #pragma unroll
        for (int j = 0; j < L/16; j++) {
            int row = j*16 + br7;
            uint32_t rb = bk + (uint32_t)(row*128);
            #pragma unroll
            for (int s = 0; s < 2; s++) {
                int unit = hh*4 + 2*s + bu;
                uint32_t b0, b1, b2, b3;
                ldsm4(b0, b1, b2, b3, rb + (uint32_t)((unit ^ (row & 7)) << 4));
                mma16816(sa[2*j],   a[s][0], a[s][1], a[s][2], a[s][3], b0, b1);
                mma16816(sa[2*j+1], a[s][0], a[s][1], a[s][2], a[s][3], b2, b3);
            }
        }
    }

    // ---- exact softmax per row ----
    float mlo = -1e30f, mhi = -1e30f;
    #pragma unroll
    for (int ni = 0; ni < L/8; ni++) {
        mlo = fmaxf(mlo, fmaxf(sa[ni][0], sa[ni][1]));
        mhi = fmaxf(mhi, fmaxf(sa[ni][2], sa[ni][3]));
    }
    #pragma unroll
    for (int o = 1; o <= 2; o <<= 1) {
        mlo = fmaxf(mlo, __shfl_xor_sync(~0u, mlo, o));
        mhi = fmaxf(mhi, __shfl_xor_sync(~0u, mhi, o));
    }
    float slo = 0.f, shi = 0.f;
    #pragma unroll
    for (int ni = 0; ni < L/8; ni++) {
        float e0 = __expf((sa[ni][0] - mlo) * scale);
        float e1 = __expf((sa[ni][1] - mlo) * scale);
        float e2 = __expf((sa[ni][2] - mhi) * scale);
        float e3 = __expf((sa[ni][3] - mhi) * scale);
        sa[ni][0] = e0; sa[ni][1] = e1; sa[ni][2] = e2; sa[ni][3] = e3;
        slo += e0 + e1; shi += e2 + e3;
    }
    #pragma unroll
    for (int o = 1; o <= 2; o <<= 1) {
        slo += __shfl_xor_sync(~0u, slo, o);
        shi += __shfl_xor_sync(~0u, shi, o);
    }
    const float ilo = 1.f / slo, ihi = 1.f / shi;

    // ---- O = P V ----
    float oa[4][4];
    #pragma unroll
    for (int ni = 0; ni < 4; ni++)
        #pragma unroll
        for (int r = 0; r < 4; r++) oa[ni][r] = 0.f;

    {
        int vr7 = (lane & 7) + (((lane >> 3) & 1) << 3);
        int vu  = lane >> 4;
        #pragma unroll
        for (int s = 0; s < L/16; s++) {
            int row = s*16 + vr7;
            uint32_t rb = bv + (uint32_t)(row*128);
            int u1 = hh*4 + vu, u2 = hh*4 + vu + 2;
            uint32_t v0,v1,v2,v3,v4,v5,v6,v7;
            ldsm4t(v0, v1, v2, v3, rb + (uint32_t)((u1 ^ (row & 7)) << 4));
            ldsm4t(v4, v5, v6, v7, rb + (uint32_t)((u2 ^ (row & 7)) << 4));
            uint32_t a0 = pack2(sa[2*s  ][0], sa[2*s  ][1]);
            uint32_t a1 = pack2(sa[2*s  ][2], sa[2*s  ][3]);
            uint32_t a2 = pack2(sa[2*s+1][0], sa[2*s+1][1]);
            uint32_t a3 = pack2(sa[2*s+1][2], sa[2*s+1][3]);
            mma16816(oa[0], a0, a1, a2, a3, v0, v1);
            mma16816(oa[1], a0, a1, a2, a3, v2, v3);
            mma16816(oa[2], a0, a1, a2, a3, v4, v5);
            mma16816(oa[3], a0, a1, a2, a3, v6, v7);
        }
    }

    // ---- normalize & store ----
    {
        int g2 = lane >> 2, t2 = (lane & 3) * 2;
        int h  = hp*2 + hh;
        int rlo = wi*16 + g2, rhi = rlo + 8;
        size_t glo = ((size_t)rlo * BtC + bt) * 256 + h*32 + t2;
        size_t ghi = ((size_t)rhi * BtC + bt) * 256 + h*32 + t2;
        #pragma unroll
        for (int ni = 0; ni < 4; ni++) {
            *(__half2*)&O[glo + ni*8] = __floats2half2_rn(oa[ni][0]*ilo, oa[ni][1]*ilo);
            *(__half2*)&O[ghi + ni*8] = __floats2half2_rn(oa[ni][2]*ihi, oa[ni][3]*ihi);
        }
    }
}

// ---------------------------------------------------------------------------
// Gathers
// ---------------------------------------------------------------------------
__global__ void __launch_bounds__(256)
gather_long(const float* __restrict__ src, const float* __restrict__ pos,
            __half* __restrict__ xqk, __half* __restrict__ xv)
{
    int t  = blockIdx.x * 4 + (threadIdx.x >> 6);
    int c4 = (threadIdx.x & 63) * 4;
    int Lc = t >> 10, Bt = t & 1023;
    int bh = Lc >> 3, w = Lc & 7;
    int b  = Bt >> 7, hh = (Bt >> 3) & 15, ww = Bt & 7;
    int n  = bh*1024 + hh*64 + w*8 + ww;
    float4 s4 = *(const float4*)(src + ((size_t)b*8192 + n)*256 + c4);
    float4 p4 = *(const float4*)(pos + (size_t)n*256 + c4);
    uint2 ov; ov.x = pack2(s4.x, s4.y); ov.y = pack2(s4.z, s4.w);
    *(uint2*)(xv + (size_t)t*256 + c4) = ov;
    uint2 oq; oq.x = pack2(s4.x+p4.x, s4.y+p4.y); oq.y = pack2(s4.z+p4.z, s4.w+p4.w);
    *(uint2*)(xqk + (size_t)t*256 + c4) = oq;
}

// ---------------------------------------------------------------------------
// Residual + scatter + LayerNorm1 (fp16 mo input; fp32 + fp16 outputs)
// ---------------------------------------------------------------------------
__global__ void __launch_bounds__(256)
resid_ln1(const float* __restrict__ src, const __half* __restrict__ mo,
          const float* __restrict__ g, const float* __restrict__ be,
          float* __restrict__ out, __half* __restrict__ out16)
{
    int tok  = blockIdx.x * 8 + (threadIdx.x >> 5);
    int lane = threadIdx.x & 31;
    int b = tok >> 13, n = tok & 8191;
    int h2 = n >> 9, bh2 = (n >> 6) & 7, ww2 = (n >> 3) & 7, w2 = n & 7;
    int ts = (h2*8 + ww2)*512 + b*64 + bh2*8 + w2;
    const float*  xs = src + (size_t)tok*256;
    const __half* ms = mo  + (size_t)ts *256;
    float v[8], sum = 0.f, sq = 0.f;
    #pragma unroll
    for (int i = 0; i < 8; i++) {
        float x = xs[lane + 32*i] + __half2float(ms[lane + 32*i]);
        v[i] = x; sum += x; sq += x*x;
    }
    #pragma unroll
    for (int o = 16; o; o >>= 1) {
        sum += __shfl_xor_sync(~0u, sum, o);
        sq  += __shfl_xor_sync(~0u, sq , o);
    }
    float mu  = sum * (1.f/256.f);
    float var = sq * (1.f/256.f) - mu*mu;
    float inv = rsqrtf(var + 1e-5f);
    #pragma unroll
    for (int i = 0; i < 8; i++) {
        int c = lane + 32*i;
        float r = (v[i] - mu) * inv * g[c] + be[c];
        out  [(size_t)tok*256 + c] = r;
        out16[(size_t)tok*256 + c] = __float2half(r);
    }
}

// ---------------------------------------------------------------------------
// Fused residual + LayerNorm2 + output transpose
// ---------------------------------------------------------------------------
__global__ void __launch_bounds__(256)
add_ln_tr(const float* __restrict__ a, const float* __restrict__ bsrc,
          const float* __restrict__ g, const float* __restrict__ be,
          float* __restrict__ out)
{
    __shared__ float tile[32][257];
    int blk = blockIdx.x;
    int b = blk >> 8, nb = blk & 255;
    int n0 = nb * 32;
    int w = threadIdx.x >> 5, lane = threadIdx.x & 31;

    #pragma unroll
    for (int i = 0; i < 4; i++) {
        int lt = w*4 + i;
        size_t tok = (size_t)b*8192 + n0 + lt;
        const float* xa = a    + tok*256;
        const float* xb = bsrc + tok*256;
        float v[8], sum = 0.f, sq = 0.f;
        #pragma unroll
        for (int e = 0; e < 8; e++) {
            float x = xa[lane + 32*e] + xb[lane + 32*e];
            v[e] = x; sum += x; sq += x*x;
        }
        #pragma unroll
        for (int o = 16; o; o >>= 1) {
            sum += __shfl_xor_sync(~0u, sum, o);
            sq  += __shfl_xor_sync(~0u, sq , o);
        }
        float mu  = sum * (1.f/256.f);
        float var = sq * (1.f/256.f) - mu*mu;
        float inv = rsqrtf(var + 1e-5f);
        #pragma unroll
        for (int e = 0; e < 8; e++) {
            int c = lane + 32*e;
            tile[lt][c] = (v[e] - mu) * inv * g[c] + be[c];
        }
    }
    __syncthreads();

    size_t ob = (size_t)b*2097152 + n0 + lane;
    #pragma unroll
    for (int k = 0; k < 32; k++) {
        int c = w*32 + k;
        out[ob + (size_t)c*8192] = tile[lane][c];
    }
}

// ---------------------------------------------------------------------------
// Launch
// ---------------------------------------------------------------------------
extern "C" void kernel_launch(void* const* d_in, const int* in_sizes, int n_in,
                              void* d_out, int out_size)
{
    const float* src        = (const float*)d_in[0];
    const float* pos        = (const float*)d_in[1];
    const float* w_in_long  = (const float*)d_in[2];
    const float* b_in_long  = (const float*)d_in[3];
    const float* w_out_long = (const float*)d_in[4];
    const float* b_out_long = (const float*)d_in[5];
    const float* w_in_short = (const float*)d_in[6];
    const float* b_in_short = (const float*)d_in[7];
    const float* w_out_short= (const float*)d_in[8];
    const float* b_out_short= (const float*)d_in[9];
    const float* w1         = (const float*)d_in[10];
    const float* b1         = (const float*)d_in[11];
    const float* w2         = (const float*)d_in[12];
    const float* b2         = (const float*)d_in[13];
    const float* g1         = (const float*)d_in[14];
    const float* beta1      = (const float*)d_in[15];
    const float* g2         = (const float*)d_in[16];
    const float* beta2      = (const float*)d_in[17];
    float* out = (float*)d_out;

    static __half *p_xqk=nullptr,*p_xv,*p_q,*p_k,*p_v,*p_attn,*p_mo16,*p_x16,*p_h;
    static __half *p_wl,*p_wol,*p_ws,*p_wos,*p_w1,*p_w2;
    static float  *p_x,*p_ff;
    static bool init_done = false;
    if (!init_done) {
        cudaGetSymbolAddress((void**)&p_xqk , g_xqk );
        cudaGetSymbolAddress((void**)&p_xv  , g_xv  );
        cudaGetSymbolAddress((void**)&p_q   , g_q   );
        cudaGetSymbolAddress((void**)&p_k   , g_k   );
        cudaGetSymbolAddress((void**)&p_v   , g_v   );
        cudaGetSymbolAddress((void**)&p_attn, g_attn);
        cudaGetSymbolAddress((void**)&p_mo16, g_mo16);
        cudaGetSymbolAddress((void**)&p_x   , g_x   );
        cudaGetSymbolAddress((void**)&p_x16 , g_x16 );
        cudaGetSymbolAddress((void**)&p_ff  , g_ff  );
        cudaGetSymbolAddress((void**)&p_h   , g_h   );
        cudaGetSymbolAddress((void**)&p_wl  , g_wl  );
        cudaGetSymbolAddress((void**)&p_wol , g_wol );
        cudaGetSymbolAddress((void**)&p_ws  , g_ws  );
        cudaGetSymbolAddress((void**)&p_wos , g_wos );
        cudaGetSymbolAddress((void**)&p_w1  , g_w1h );
        cudaGetSymbolAddress((void**)&p_w2  , g_w2h );
        cudaFuncSetAttribute((const void*)gemm_h<0,0>,
            cudaFuncAttributeMaxDynamicSharedMemorySize, GEMMH_SMEM);
        cudaFuncSetAttribute((const void*)gemm_h<0,1>,
            cudaFuncAttributeMaxDynamicSharedMemorySize, GEMMH_SMEM);
        cudaFuncSetAttribute((const void*)gemm_h<1,1>,
            cudaFuncAttributeMaxDynamicSharedMemorySize, GEMMH_SMEM);
        cudaFuncSetAttribute((const void*)gemm_h<2,1>,
            cudaFuncAttributeMaxDynamicSharedMemorySize, GEMMH_SMEM);
        cudaFuncSetAttribute((const void*)gemm_h<3,1>,
            cudaFuncAttributeMaxDynamicSharedMemorySize, GEMMH_SMEM);
        init_done = true;
    }

    // ---- weight conversion ----
    f2h_all<<<1024, 256>>>(w_in_long, w_out_long, w_in_short, w_out_short, w1, w2);

    const dim3 gQKV(TOK/128, 6);
    const dim3 g256(TOK/128, 2);
    const dim3 gHID(TOK/128, 8);

    // ---- long-range MHA ----
    gather_long<<<TOK/4, 256>>>(src, pos, p_xqk, p_xv);
    gemm_h<2,1><<<gQKV, 256, GEMMH_SMEM>>>(p_xqk, p_xv, p_wl, b_in_long, nullptr,
                                           p_q, p_k, p_v, TOK, 768, CDIM);
    attn_tc2<64><<<1024*4, 256>>>(p_q, p_k, p_v, p_attn, 1024);
    // out-proj long with FUSED short-gather scatter epilogue
    gemm_h<3,1><<<g256, 256, GEMMH_SMEM>>>(p_attn, nullptr, p_wol, b_out_long, pos,
                                           p_xqk, p_xv, nullptr, TOK, CDIM, CDIM);

    // ---- short-range MHA ----
    gemm_h<2,1><<<gQKV, 256, GEMMH_SMEM>>>(p_xqk, p_xv, p_ws, b_in_short, nullptr,
                                           p_q, p_k, p_v, TOK, 768, CDIM);
    attn_tc2<128><<<512*4, 512>>>(p_q, p_k, p_v, p_attn, 512);
    gemm_h<0,1><<<g256, 256, GEMMH_SMEM>>>(p_attn, nullptr, p_wos, b_out_short, nullptr,
                                           p_mo16, nullptr, nullptr, TOK, CDIM, CDIM);

    // ---- residual + LN1 ----
    resid_ln1<<<TOK/8, 256>>>(src, p_mo16, g1, beta1, p_x, p_x16);

    // ---- FFN ----
    gemm_h<1,1><<<gHID, 256, GEMMH_SMEM>>>(p_x16, nullptr, p_w1, b1, nullptr,
                                           p_h, nullptr, nullptr, TOK, HID, CDIM);
    gemm_h<0,0><<<g256, 256, GEMMH_SMEM>>>(p_h, nullptr, p_w2, b2, nullptr,
                                           p_ff, nullptr, nullptr, TOK, CDIM, HID);

    // ---- residual + LN2 + output transpose (fused) ----
    add_ln_tr<<<2048, 256>>>(p_x, p_ff, g2, beta2, out);
}